// round 5
// baseline (speedup 1.0000x reference)
#include <cuda_runtime.h>
#include <math.h>

// ---------------- problem dims ----------------
#define F_  1024
#define H_  16
#define D_  18
#define P_  64
#define B_  128
#define T_  8192      // B*P tokens
#define C3F 3072
#define NC  23
#define MH  4096

// ---------------- device scratch (no runtime allocation allowed) ----------------
__device__ float g_qln[2][F_];                 // LN'd queries: [0]=channel, [1]=cls
__device__ float g_qh[2][F_];                  // projected queries (H*HD flat)
__device__ float g_wkeff[2][H_ * F_];          // folded key weights per head
__device__ float g_bkeff[2][H_];               // folded key bias per head
__device__ float g_mixed[(size_t)H_ * T_ * F_];// [h][t][f]  (512 MB)
__device__ float g_pooled[(size_t)T_ * F_];    // stage1 pooled (pre out-proj)
__device__ float g_z[(size_t)T_ * F_];         // pooled @ ch_out_w + b
__device__ float g_kv[(size_t)T_ * F_];        // ln(ln(z,cn),pnp)
__device__ float g_mixed2[H_ * B_ * F_];       // [h][b][f]
__device__ float g_pooled2[B_ * F_];
__device__ float g_p2[B_ * F_];
__device__ float g_p2ln[B_ * F_];
__device__ float g_hid[B_ * MH];

// ---------------- helpers ----------------
__device__ __forceinline__ float block_sum_256(float v, float* red) {
    #pragma unroll
    for (int o = 16; o; o >>= 1) v += __shfl_xor_sync(0xffffffffu, v, o);
    int w = threadIdx.x >> 5;
    if ((threadIdx.x & 31) == 0) red[w] = v;
    __syncthreads();
    float s = red[0];
    #pragma unroll
    for (int i = 1; i < 8; i++) s += red[i];
    __syncthreads();
    return s;
}

// ---------------- generic 1024-wide row LayerNorm ----------------
__global__ __launch_bounds__(256) void k_ln_row(const float* __restrict__ src,
                                                const float* __restrict__ g,
                                                const float* __restrict__ b,
                                                float* __restrict__ dst) {
    __shared__ float red[8];
    size_t row = blockIdx.x;
    int tid = threadIdx.x;
    float4 v = ((const float4*)src)[row * 256 + tid];
    float m = block_sum_256(v.x + v.y + v.z + v.w, red) * (1.f / 1024.f);
    float dx = v.x - m, dy = v.y - m, dz = v.z - m, dw = v.w - m;
    float var = block_sum_256(dx*dx + dy*dy + dz*dz + dw*dw, red) * (1.f / 1024.f);
    float rs = rsqrtf(var + 1e-5f);
    float4 gv = ((const float4*)g)[tid];
    float4 bv = ((const float4*)b)[tid];
    float4 o;
    o.x = dx * rs * gv.x + bv.x;
    o.y = dy * rs * gv.y + bv.y;
    o.z = dz * rs * gv.z + bv.z;
    o.w = dw * rs * gv.w + bv.w;
    ((float4*)dst)[row * 256 + tid] = o;
}

// ---------------- qh = q_ln @ W[:, :F] + b[:F], both sides ----------------
__global__ __launch_bounds__(128) void k_qh(const float* __restrict__ chw,
                                            const float* __restrict__ chb,
                                            const float* __restrict__ tw,
                                            const float* __restrict__ tb) {
    int side = blockIdx.y;
    const float* W  = side ? tw : chw;
    const float* bb = side ? tb : chb;
    const float* q  = g_qln[side];
    __shared__ float qs[F_];
    int tid = threadIdx.x;
    for (int i = tid; i < F_; i += 128) qs[i] = q[i];
    __syncthreads();
    int j = blockIdx.x * 128 + tid;
    float a0 = 0.f, a1 = 0.f, a2 = 0.f, a3 = 0.f;
    for (int f = 0; f < F_; f += 4) {
        a0 = fmaf(qs[f    ], W[(size_t)(f    ) * C3F + j], a0);
        a1 = fmaf(qs[f + 1], W[(size_t)(f + 1) * C3F + j], a1);
        a2 = fmaf(qs[f + 2], W[(size_t)(f + 2) * C3F + j], a2);
        a3 = fmaf(qs[f + 3], W[(size_t)(f + 3) * C3F + j], a3);
    }
    g_qh[side][j] = a0 + a1 + a2 + a3 + bb[j];
}

// ---------------- fold qh into W_k: wkeff[h][f], bkeff[h] ----------------
__global__ __launch_bounds__(128) void k_fold(const float* __restrict__ chw,
                                              const float* __restrict__ chb,
                                              const float* __restrict__ tw,
                                              const float* __restrict__ tb) {
    int side = blockIdx.y, f = blockIdx.x, tid = threadIdx.x;
    const float* W  = side ? tw : chw;
    const float* qh = g_qh[side];
    __shared__ float wrow[F_];
    for (int i = tid; i < F_; i += 128) wrow[i] = W[(size_t)f * C3F + F_ + i];
    __syncthreads();
    int h = tid >> 3, i8 = tid & 7;
    float s = 0.f;
    #pragma unroll
    for (int d = 0; d < 8; d++) s += wrow[h * 64 + i8 * 8 + d] * qh[h * 64 + i8 * 8 + d];
    s += __shfl_down_sync(0xffffffffu, s, 4, 8);
    s += __shfl_down_sync(0xffffffffu, s, 2, 8);
    s += __shfl_down_sync(0xffffffffu, s, 1, 8);
    if (i8 == 0) g_wkeff[side][h * F_ + f] = s;
    if (f == 0 && tid < H_) {
        const float* bb = side ? tb : chb;
        float bs = 0.f;
        for (int d = 0; d < 64; d++) bs += bb[F_ + tid * 64 + d] * qh[tid * 64 + d];
        g_bkeff[side][tid] = bs;
    }
}

// ---------------- fused main pass: scores -> softmax(D) -> channel mix ----------------
// grid (P, B), 256 threads. dyn smem: xs[18*1024] wk[16*1024] sc[288] attnT[288]
#define SMEM_MAIN ((D_ * F_ + H_ * F_ + 288 + 288) * 4)
__global__ __launch_bounds__(256) void k_main(const float* __restrict__ x) {
    extern __shared__ float sm[];
    float* xs    = sm;
    float* wk    = xs + D_ * F_;
    float* sc    = wk + H_ * F_;
    float* attnT = sc + 288;

    int p = blockIdx.x, b = blockIdx.y;
    int tid = threadIdx.x;
    int t = b * P_ + p;

    const float4* xg = (const float4*)x;
    #pragma unroll
    for (int k = 0; k < D_; k++)
        ((float4*)xs)[k * 256 + tid] = xg[((size_t)(b * D_ + k) * P_ + p) * 256 + tid];
    const float4* wg = (const float4*)g_wkeff[0];
    #pragma unroll
    for (int i = 0; i < 16; i++) {
        int idx = tid + i * 256;
        ((float4*)wk)[idx] = wg[idx];
    }
    __syncthreads();

    // scores: 288 (h,k) pairs over 8 warps
    int w = tid >> 5, lane = tid & 31;
    for (int j = 0; j < 36; j++) {
        int pair = w + 8 * j;
        int h = pair / D_, k = pair % D_;
        const float4* xr = (const float4*)(xs + k * F_);
        const float4* wr = (const float4*)(wk + h * F_);
        float s = 0.f;
        #pragma unroll
        for (int i = 0; i < 8; i++) {
            float4 a = xr[lane + 32 * i];
            float4 bv = wr[lane + 32 * i];
            s = fmaf(a.x, bv.x, s); s = fmaf(a.y, bv.y, s);
            s = fmaf(a.z, bv.z, s); s = fmaf(a.w, bv.w, s);
        }
        #pragma unroll
        for (int o = 16; o; o >>= 1) s += __shfl_xor_sync(0xffffffffu, s, o);
        if (lane == 0) sc[pair] = (s + g_bkeff[0][h]) * 0.125f;
    }
    __syncthreads();

    if (tid < H_) {
        int h = tid;
        float mx = -1e30f;
        #pragma unroll
        for (int k = 0; k < D_; k++) mx = fmaxf(mx, sc[h * D_ + k]);
        float e[D_], ssum = 0.f;
        #pragma unroll
        for (int k = 0; k < D_; k++) { e[k] = expf(sc[h * D_ + k] - mx); ssum += e[k]; }
        float inv = 1.f / ssum;
        #pragma unroll
        for (int k = 0; k < D_; k++) attnT[k * H_ + h] = e[k] * inv;   // transposed
    }
    __syncthreads();

    // mixed[h][f] = sum_k attn[h][k] * xs[k][f]
    float4 acc[H_];
    #pragma unroll
    for (int h = 0; h < H_; h++) acc[h] = make_float4(0.f, 0.f, 0.f, 0.f);
    #pragma unroll
    for (int k = 0; k < D_; k++) {
        float4 xv = ((const float4*)xs)[k * 256 + tid];
        const float4* at = (const float4*)(attnT + k * H_);
        float4 q0 = at[0], q1 = at[1], q2 = at[2], q3 = at[3];
        float av[16] = { q0.x, q0.y, q0.z, q0.w, q1.x, q1.y, q1.z, q1.w,
                         q2.x, q2.y, q2.z, q2.w, q3.x, q3.y, q3.z, q3.w };
        #pragma unroll
        for (int h = 0; h < H_; h++) {
            acc[h].x = fmaf(av[h], xv.x, acc[h].x);
            acc[h].y = fmaf(av[h], xv.y, acc[h].y);
            acc[h].z = fmaf(av[h], xv.z, acc[h].z);
            acc[h].w = fmaf(av[h], xv.w, acc[h].w);
        }
    }
    #pragma unroll
    for (int h = 0; h < H_; h++)
        ((float4*)g_mixed)[((size_t)h * T_ + t) * 256 + tid] = acc[h];
}

// ---------------- generic tiled SGEMM: C = A@B + bias, optional exact GELU ----------------
// BM=128 BN=64 BK=16, 256 threads, 8x4 per thread. M%128==0, N%64==0, K%16==0.
__global__ __launch_bounds__(256) void k_gemm(
    const float* __restrict__ A, int lda, long long sA,
    const float* __restrict__ Bm, int ldb, long long sB,
    const float* __restrict__ bias, long long sBias,
    float* __restrict__ C, int ldc, long long sC,
    int K, int act) {
    __shared__ float As[128 * 16];
    __shared__ float Bs[16 * 64];
    long long z = blockIdx.z;
    A += z * sA; Bm += z * sB; C += z * sC; bias += z * sBias;
    int tM = blockIdx.y * 128, tN = blockIdx.x * 64;
    int tid = threadIdx.x, tn = tid & 15, tm = tid >> 4;
    float acc[8][4];
    #pragma unroll
    for (int i = 0; i < 8; i++)
        #pragma unroll
        for (int j = 0; j < 4; j++) acc[i][j] = 0.f;

    for (int k0 = 0; k0 < K; k0 += 16) {
        #pragma unroll
        for (int i = 0; i < 2; i++) {
            int lin = tid + i * 256;
            int r = lin >> 2, c4 = lin & 3;
            float4 v = *(const float4*)(A + (size_t)(tM + r) * lda + k0 + c4 * 4);
            *(float4*)(As + r * 16 + c4 * 4) = v;
        }
        {
            int r = tid >> 4, c4 = tid & 15;
            float4 v = *(const float4*)(Bm + (size_t)(k0 + r) * ldb + tN + c4 * 4);
            *(float4*)(Bs + r * 64 + c4 * 4) = v;
        }
        __syncthreads();
        #pragma unroll
        for (int kk = 0; kk < 16; kk++) {
            float4 bf = *(const float4*)(Bs + kk * 64 + tn * 4);
            #pragma unroll
            for (int mi = 0; mi < 8; mi++) {
                float a = As[(tm * 8 + mi) * 16 + kk];
                acc[mi][0] = fmaf(a, bf.x, acc[mi][0]);
                acc[mi][1] = fmaf(a, bf.y, acc[mi][1]);
                acc[mi][2] = fmaf(a, bf.z, acc[mi][2]);
                acc[mi][3] = fmaf(a, bf.w, acc[mi][3]);
            }
        }
        __syncthreads();
    }
    float4 bv = *(const float4*)(bias + tN + tn * 4);
    #pragma unroll
    for (int mi = 0; mi < 8; mi++) {
        int row = tM + tm * 8 + mi;
        float4 o;
        o.x = acc[mi][0] + bv.x; o.y = acc[mi][1] + bv.y;
        o.z = acc[mi][2] + bv.z; o.w = acc[mi][3] + bv.w;
        if (act) {
            o.x = 0.5f * o.x * (1.f + erff(o.x * 0.70710678118654752f));
            o.y = 0.5f * o.y * (1.f + erff(o.y * 0.70710678118654752f));
            o.z = 0.5f * o.z * (1.f + erff(o.z * 0.70710678118654752f));
            o.w = 0.5f * o.w * (1.f + erff(o.w * 0.70710678118654752f));
        }
        *(float4*)(C + (size_t)row * ldc + tN + tn * 4) = o;
    }
}

// ---------------- kv = ln(ln(z, cn), pnp) ----------------
__global__ __launch_bounds__(256) void k_lnln(const float* __restrict__ g1,
                                              const float* __restrict__ b1,
                                              const float* __restrict__ g2,
                                              const float* __restrict__ b2) {
    __shared__ float red[8];
    size_t row = blockIdx.x;
    int tid = threadIdx.x;
    float4 v = ((const float4*)g_z)[row * 256 + tid];
    float m = block_sum_256(v.x + v.y + v.z + v.w, red) * (1.f / 1024.f);
    float dx = v.x - m, dy = v.y - m, dz = v.z - m, dw = v.w - m;
    float var = block_sum_256(dx*dx + dy*dy + dz*dz + dw*dw, red) * (1.f / 1024.f);
    float rs = rsqrtf(var + 1e-5f);
    float4 g1v = ((const float4*)g1)[tid], b1v = ((const float4*)b1)[tid];
    float yx = dx * rs * g1v.x + b1v.x, yy = dy * rs * g1v.y + b1v.y;
    float yz = dz * rs * g1v.z + b1v.z, yw = dw * rs * g1v.w + b1v.w;
    float m2 = block_sum_256(yx + yy + yz + yw, red) * (1.f / 1024.f);
    float ex = yx - m2, ey = yy - m2, ez = yz - m2, ew = yw - m2;
    float var2 = block_sum_256(ex*ex + ey*ey + ez*ez + ew*ew, red) * (1.f / 1024.f);
    float rs2 = rsqrtf(var2 + 1e-5f);
    float4 g2v = ((const float4*)g2)[tid], b2v = ((const float4*)b2)[tid];
    float4 o;
    o.x = ex * rs2 * g2v.x + b2v.x;
    o.y = ey * rs2 * g2v.y + b2v.y;
    o.z = ez * rs2 * g2v.z + b2v.z;
    o.w = ew * rs2 * g2v.w + b2v.w;
    ((float4*)g_kv)[row * 256 + tid] = o;
}

// ---------------- stage-2: scores over P, softmax, temporal mix ----------------
__global__ __launch_bounds__(256) void k_sc2mix() {
    __shared__ float sc[H_ * P_];
    int b = blockIdx.x, tid = threadIdx.x, w = tid >> 5, lane = tid & 31;
    for (int j = 0; j < 128; j++) {
        int pair = w + 8 * j;                  // 0..1023
        int h = pair >> 6, p = pair & 63;
        const float4* kr = (const float4*)(g_kv + (size_t)(b * P_ + p) * F_);
        const float4* wr = (const float4*)(g_wkeff[1] + h * F_);
        float s = 0.f;
        #pragma unroll
        for (int i = 0; i < 8; i++) {
            float4 a = kr[lane + 32 * i];
            float4 bv = wr[lane + 32 * i];
            s = fmaf(a.x, bv.x, s); s = fmaf(a.y, bv.y, s);
            s = fmaf(a.z, bv.z, s); s = fmaf(a.w, bv.w, s);
        }
        #pragma unroll
        for (int o = 16; o; o >>= 1) s += __shfl_xor_sync(0xffffffffu, s, o);
        if (lane == 0) sc[h * P_ + p] = (s + g_bkeff[1][h]) * 0.125f;
    }
    __syncthreads();
    if (tid < H_) {
        int h = tid;
        float mx = -1e30f;
        for (int p = 0; p < P_; p++) mx = fmaxf(mx, sc[h * P_ + p]);
        float ssum = 0.f;
        for (int p = 0; p < P_; p++) { float e = expf(sc[h * P_ + p] - mx); sc[h * P_ + p] = e; ssum += e; }
        float inv = 1.f / ssum;
        for (int p = 0; p < P_; p++) sc[h * P_ + p] *= inv;
    }
    __syncthreads();
    float4 acc[H_];
    #pragma unroll
    for (int h = 0; h < H_; h++) acc[h] = make_float4(0.f, 0.f, 0.f, 0.f);
    for (int p = 0; p < P_; p++) {
        float4 xv = ((const float4*)g_kv)[(size_t)(b * P_ + p) * 256 + tid];
        #pragma unroll
        for (int h = 0; h < H_; h++) {
            float a = sc[h * P_ + p];
            acc[h].x = fmaf(a, xv.x, acc[h].x);
            acc[h].y = fmaf(a, xv.y, acc[h].y);
            acc[h].z = fmaf(a, xv.z, acc[h].z);
            acc[h].w = fmaf(a, xv.w, acc[h].w);
        }
    }
    #pragma unroll
    for (int h = 0; h < H_; h++)
        ((float4*)g_mixed2)[(size_t)(h * B_ + b) * 256 + tid] = acc[h];
}

// ---------------- final classifier: logits = hid @ w2 + b2 ----------------
__global__ __launch_bounds__(256) void k_logits(const float* __restrict__ w2,
                                                const float* __restrict__ b2,
                                                float* __restrict__ out) {
    int b = blockIdx.x, tid = threadIdx.x, w = tid >> 5, lane = tid & 31;
    const float* hrow = g_hid + (size_t)b * MH;
    for (int c = w; c < NC; c += 8) {
        float s = 0.f;
        for (int i = lane; i < MH; i += 32) s = fmaf(hrow[i], w2[(size_t)i * NC + c], s);
        #pragma unroll
        for (int o = 16; o; o >>= 1) s += __shfl_xor_sync(0xffffffffu, s, o);
        if (lane == 0) out[b * NC + c] = s + b2[c];
    }
}

// ---------------- launch ----------------
extern "C" void kernel_launch(void* const* d_in, const int* in_sizes, int n_in,
                              void* d_out, int out_size) {
    (void)in_sizes; (void)n_in; (void)out_size;
    const float* x    = (const float*)d_in[0];
    const float* chq  = (const float*)d_in[1];
    const float* clq  = (const float*)d_in[2];
    const float* chw  = (const float*)d_in[3];
    const float* chb  = (const float*)d_in[4];
    const float* chow = (const float*)d_in[5];
    const float* chob = (const float*)d_in[6];
    const float* tw   = (const float*)d_in[7];
    const float* tb   = (const float*)d_in[8];
    const float* tow  = (const float*)d_in[9];
    const float* tob  = (const float*)d_in[10];
    const float* qn_g = (const float*)d_in[11];
    const float* qn_b = (const float*)d_in[12];
    const float* cn_g = (const float*)d_in[13];
    const float* cn_b = (const float*)d_in[14];
    const float* pnc_g = (const float*)d_in[15];
    const float* pnc_b = (const float*)d_in[16];
    const float* pnp_g = (const float*)d_in[17];
    const float* pnp_b = (const float*)d_in[18];
    const float* pon_g = (const float*)d_in[19];
    const float* pon_b = (const float*)d_in[20];
    const float* w1 = (const float*)d_in[21];
    const float* b1 = (const float*)d_in[22];
    const float* w2 = (const float*)d_in[23];
    const float* b2 = (const float*)d_in[24];
    float* out = (float*)d_out;

    float *p_qln, *p_mixed, *p_pooled, *p_z, *p_mixed2, *p_pooled2, *p_p2, *p_p2ln, *p_hid;
    cudaGetSymbolAddress((void**)&p_qln,     g_qln);
    cudaGetSymbolAddress((void**)&p_mixed,   g_mixed);
    cudaGetSymbolAddress((void**)&p_pooled,  g_pooled);
    cudaGetSymbolAddress((void**)&p_z,       g_z);
    cudaGetSymbolAddress((void**)&p_mixed2,  g_mixed2);
    cudaGetSymbolAddress((void**)&p_pooled2, g_pooled2);
    cudaGetSymbolAddress((void**)&p_p2,      g_p2);
    cudaGetSymbolAddress((void**)&p_p2ln,    g_p2ln);
    cudaGetSymbolAddress((void**)&p_hid,     g_hid);

    cudaFuncSetAttribute(k_main, cudaFuncAttributeMaxDynamicSharedMemorySize, SMEM_MAIN);

    // query LayerNorms
    k_ln_row<<<1, 256>>>(chq, qn_g, qn_b, p_qln);
    k_ln_row<<<1, 256>>>(clq, pnc_g, pnc_b, p_qln + F_);
    // project queries, fold into key weights
    k_qh<<<dim3(8, 2), 128>>>(chw, chb, tw, tb);
    k_fold<<<dim3(1024, 2), 128>>>(chw, chb, tw, tb);
    // stage 1 fused: scores + softmax + channel mix
    k_main<<<dim3(P_, B_), 256, SMEM_MAIN>>>(x);
    // pooled = mixed_h @ Wv_h + bv (batched over heads)
    k_gemm<<<dim3(1, T_ / 128, H_), 256>>>(p_mixed, F_, (long long)T_ * F_,
                                           chw + 2 * F_, C3F, 64,
                                           chb + 2 * F_, 64,
                                           p_pooled, F_, 64, F_, 0);
    // z = pooled @ ch_out_w + ch_out_b
    k_gemm<<<dim3(F_ / 64, T_ / 128, 1), 256>>>(p_pooled, F_, 0,
                                                chow, F_, 0, chob, 0,
                                                p_z, F_, 0, F_, 0);
    // kv = ln(ln(z, cn), pnp)
    k_lnln<<<T_, 256>>>(cn_g, cn_b, pnp_g, pnp_b);
    // stage 2 fused: temporal scores + softmax + mix
    k_sc2mix<<<B_, 256>>>();
    // pooled2 = mixed2_h @ Wv2_h + bv2
    k_gemm<<<dim3(1, 1, H_), 256>>>(p_mixed2, F_, (long long)B_ * F_,
                                    tw + 2 * F_, C3F, 64,
                                    tb + 2 * F_, 64,
                                    p_pooled2, F_, 64, F_, 0);
    // p2 = pooled2 @ t_out_w + t_out_b
    k_gemm<<<dim3(F_ / 64, 1, 1), 256>>>(p_pooled2, F_, 0,
                                         tow, F_, 0, tob, 0,
                                         p_p2, F_, 0, F_, 0);
    // p2ln = ln(p2, pon)
    k_ln_row<<<B_, 256>>>(p_p2, pon_g, pon_b, p_p2ln);
    // hid = gelu(p2ln @ w1 + b1)
    k_gemm<<<dim3(MH / 64, 1, 1), 256>>>(p_p2ln, F_, 0,
                                         w1, MH, 0, b1, 0,
                                         p_hid, MH, 0, F_, 1);
    // logits
    k_logits<<<B_, 256>>>(w2, b2, out);
}

// round 8
// speedup vs baseline: 1.1879x; 1.1879x over previous
#include <cuda_runtime.h>
#include <cuda_bf16.h>
#include <math.h>
#include <stdint.h>

#define F_  1024
#define H_  16
#define D_  18
#define P_  64
#define B_  128
#define T_  8192
#define C3F 3072
#define NC  23
#define MH  4096

__device__ float g_qln[2][F_];
__device__ float g_qh[2][F_];
__device__ float g_wkeff[2][H_ * F_];
__device__ float g_bkeff[2][H_];
__device__ float g_mixed[(size_t)H_ * T_ * F_];
__device__ float g_pooled[(size_t)T_ * F_];
__device__ float g_z[(size_t)T_ * F_];
__device__ float g_kv[(size_t)T_ * F_];
__device__ float g_mixed2[H_ * B_ * F_];
__device__ float g_pooled2[B_ * F_];
__device__ float g_p2[B_ * F_];
__device__ float g_p2ln[B_ * F_];
__device__ float g_hid[B_ * MH];
// pre-transposed + split weights, [N][1024] bf16, K contiguous
__device__ __align__(16) __nv_bfloat16 g_wvT_h[F_ * F_],  g_wvT_l[F_ * F_];
__device__ __align__(16) __nv_bfloat16 g_chowT_h[F_ * F_], g_chowT_l[F_ * F_];
__device__ __align__(16) __nv_bfloat16 g_wv2T_h[F_ * F_], g_wv2T_l[F_ * F_];
__device__ __align__(16) __nv_bfloat16 g_towT_h[F_ * F_], g_towT_l[F_ * F_];
__device__ __align__(16) __nv_bfloat16 g_w1T_h[MH * F_],  g_w1T_l[MH * F_];

__device__ __forceinline__ uint32_t smem_u32(const void* p) {
    uint32_t a;
    asm("{ .reg .u64 t; cvta.to.shared.u64 t, %1; cvt.u32.u64 %0, t; }" : "=r"(a) : "l"(p));
    return a;
}
__device__ __forceinline__ void ldsm4(uint32_t& r0, uint32_t& r1, uint32_t& r2, uint32_t& r3, uint32_t a) {
    asm volatile("ldmatrix.sync.aligned.m8n8.x4.shared.b16 {%0,%1,%2,%3}, [%4];"
        : "=r"(r0), "=r"(r1), "=r"(r2), "=r"(r3) : "r"(a));
}
__device__ __forceinline__ void mma_bf16(float* c, const uint32_t* a, uint32_t b0, uint32_t b1) {
    asm volatile("mma.sync.aligned.m16n8k16.row.col.f32.bf16.bf16.f32 "
        "{%0,%1,%2,%3},{%4,%5,%6,%7},{%8,%9},{%0,%1,%2,%3};"
        : "+f"(c[0]), "+f"(c[1]), "+f"(c[2]), "+f"(c[3])
        : "r"(a[0]), "r"(a[1]), "r"(a[2]), "r"(a[3]), "r"(b0), "r"(b1));
}
__device__ __forceinline__ void sp2(float v0, float v1, uint32_t& h, uint32_t& l) {
    __nv_bfloat16 h0 = __float2bfloat16(v0), h1 = __float2bfloat16(v1);
    __nv_bfloat16 l0 = __float2bfloat16(v0 - __bfloat162float(h0));
    __nv_bfloat16 l1 = __float2bfloat16(v1 - __bfloat162float(h1));
    h = ((uint32_t)__bfloat16_as_ushort(h1) << 16) | __bfloat16_as_ushort(h0);
    l = ((uint32_t)__bfloat16_as_ushort(l1) << 16) | __bfloat16_as_ushort(l0);
}
__device__ __forceinline__ float block_sum_256(float v, float* red) {
    #pragma unroll
    for (int o = 16; o; o >>= 1) v += __shfl_xor_sync(0xffffffffu, v, o);
    int w = threadIdx.x >> 5;
    if ((threadIdx.x & 31) == 0) red[w] = v;
    __syncthreads();
    float s = red[0];
    #pragma unroll
    for (int i = 1; i < 8; i++) s += red[i];
    __syncthreads();
    return s;
}

// ---------------- weight transpose + split ----------------
__global__ __launch_bounds__(256) void k_trsplit(const float* __restrict__ src, int lds, int ofs,
                                                 __nv_bfloat16* __restrict__ dh,
                                                 __nv_bfloat16* __restrict__ dl) {
    __shared__ float t[32][33];
    int k0 = blockIdx.x * 32, n0 = blockIdx.y * 32;
    int tx = threadIdx.x & 31, ty = threadIdx.x >> 5;
    #pragma unroll
    for (int j = 0; j < 4; j++)
        t[ty + j * 8][tx] = src[(size_t)(k0 + ty + j * 8) * lds + ofs + n0 + tx];
    __syncthreads();
    #pragma unroll
    for (int j = 0; j < 4; j++) {
        int r = ty + j * 8;
        float v = t[tx][r];
        __nv_bfloat16 h = __float2bfloat16(v);
        __nv_bfloat16 l = __float2bfloat16(v - __bfloat162float(h));
        size_t o = (size_t)(n0 + r) * F_ + k0 + tx;
        dh[o] = h; dl[o] = l;
    }
}

// ---------------- mma.sync split-bf16 GEMM: C = A(f32) @ BT^T + bias ----------------
// block tile 128x64, 8 warps (4m x 2n), warp tile 32x32, K=1024 in chunks of 16.
// smem rows padded to 24 halves (48B) -> conflict-free ldmatrix.
__global__ __launch_bounds__(256) void k_mma(
    const float* __restrict__ A, int lda, long long sA,
    const __nv_bfloat16* __restrict__ BTh, const __nv_bfloat16* __restrict__ BTl, long long sB,
    const float* __restrict__ bias, long long sBias,
    float* __restrict__ C, int ldc, long long sC, int act)
{
    __shared__ __nv_bfloat16 s[9216];   // Ah[128*24] Al[128*24] Bh[64*24] Bl[64*24]
    int z = blockIdx.z;
    A   += (size_t)z * sA;
    BTh += (size_t)z * sB; BTl += (size_t)z * sB;
    const float* bz = bias + (size_t)z * sBias;
    float* Cz = C + (size_t)z * sC;
    const int tM = blockIdx.y * 128, tN = blockIdx.x * 64;
    const int t = threadIdx.x, wid = t >> 5, lane = t & 31;
    const int m_idx = wid >> 1, n_idx = wid & 1;
    uint32_t* s32 = (uint32_t*)s;
    uint32_t sbase = smem_u32(s);

    // per-thread load/store setup
    const int arow = t >> 1, akh = t & 1;
    const float* ag = A + (size_t)(tM + arow) * lda + akh * 8;
    const int aidx = arow * 12 + akh * 4;                      // u32 index into Ah
    const int brow = (t & 127) >> 1, bkh = t & 1;
    const __nv_bfloat16* bg = ((t < 128) ? BTh : BTl) + (size_t)(tN + brow) * F_ + bkh * 8;
    const int bidx = 3072 + ((t >= 128) ? 768 : 0) + brow * 12 + bkh * 4;

    // ldmatrix addresses
    uint32_t adA[2], adB[2];
    #pragma unroll
    for (int ti = 0; ti < 2; ti++) {
        int r = m_idx * 32 + ti * 16 + (lane & 15);
        adA[ti] = sbase + r * 48 + (lane >> 4) * 16;
    }
    #pragma unroll
    for (int gi = 0; gi < 2; gi++) {
        int mtx = lane >> 3;
        int nr = n_idx * 32 + gi * 16 + (mtx >> 1) * 8 + (lane & 7);
        adB[gi] = sbase + 6144 * 2 + nr * 48 + (mtx & 1) * 16;
    }

    float acc[2][4][4];
    #pragma unroll
    for (int i = 0; i < 2; i++)
        #pragma unroll
        for (int j = 0; j < 4; j++)
            #pragma unroll
            for (int k = 0; k < 4; k++) acc[i][j][k] = 0.f;

    float4 pa0 = *(const float4*)(ag);
    float4 pa1 = *(const float4*)(ag + 4);
    uint4  pb  = *(const uint4*)(bg);

    for (int c = 0; c < 64; c++) {
        __syncthreads();
        // split A regs -> smem hi/lo
        uint32_t h, l;
        sp2(pa0.x, pa0.y, h, l); s32[aidx]          = h; s32[1536 + aidx]     = l;
        sp2(pa0.z, pa0.w, h, l); s32[aidx + 1]      = h; s32[1536 + aidx + 1] = l;
        sp2(pa1.x, pa1.y, h, l); s32[aidx + 2]      = h; s32[1536 + aidx + 2] = l;
        sp2(pa1.z, pa1.w, h, l); s32[aidx + 3]      = h; s32[1536 + aidx + 3] = l;
        s32[bidx] = pb.x; s32[bidx + 1] = pb.y; s32[bidx + 2] = pb.z; s32[bidx + 3] = pb.w;
        __syncthreads();
        if (c < 63) {
            pa0 = *(const float4*)(ag + (c + 1) * 16);
            pa1 = *(const float4*)(ag + (c + 1) * 16 + 4);
            pb  = *(const uint4*)(bg + (c + 1) * 16);
        }
        uint32_t Ah[2][4], Al[2][4], Bh[2][4], Bl[2][4];
        #pragma unroll
        for (int ti = 0; ti < 2; ti++) {
            ldsm4(Ah[ti][0], Ah[ti][1], Ah[ti][2], Ah[ti][3], adA[ti]);
            ldsm4(Al[ti][0], Al[ti][1], Al[ti][2], Al[ti][3], adA[ti] + 3072 * 2);
        }
        #pragma unroll
        for (int gi = 0; gi < 2; gi++) {
            ldsm4(Bh[gi][0], Bh[gi][1], Bh[gi][2], Bh[gi][3], adB[gi]);
            ldsm4(Bl[gi][0], Bl[gi][1], Bl[gi][2], Bl[gi][3], adB[gi] + 1536 * 2);
        }
        #pragma unroll
        for (int ti = 0; ti < 2; ti++)
            #pragma unroll
            for (int gi = 0; gi < 2; gi++)
                #pragma unroll
                for (int sub = 0; sub < 2; sub++) {
                    int tn = gi * 2 + sub;
                    mma_bf16(acc[ti][tn], Ah[ti], Bh[gi][2 * sub], Bh[gi][2 * sub + 1]);
                    mma_bf16(acc[ti][tn], Ah[ti], Bl[gi][2 * sub], Bl[gi][2 * sub + 1]);
                    mma_bf16(acc[ti][tn], Al[ti], Bh[gi][2 * sub], Bh[gi][2 * sub + 1]);
                }
    }

    // epilogue
    const int g = lane >> 2, tg = lane & 3;
    #pragma unroll
    for (int ti = 0; ti < 2; ti++) {
        int r0 = tM + m_idx * 32 + ti * 16 + g;
        #pragma unroll
        for (int tn = 0; tn < 4; tn++) {
            int col = tN + n_idx * 32 + tn * 8 + tg * 2;
            float b0 = bz[col], b1 = bz[col + 1];
            float v0 = acc[ti][tn][0] + b0, v1 = acc[ti][tn][1] + b1;
            float v2 = acc[ti][tn][2] + b0, v3 = acc[ti][tn][3] + b1;
            if (act) {
                v0 = 0.5f * v0 * (1.f + erff(v0 * 0.70710678118654752f));
                v1 = 0.5f * v1 * (1.f + erff(v1 * 0.70710678118654752f));
                v2 = 0.5f * v2 * (1.f + erff(v2 * 0.70710678118654752f));
                v3 = 0.5f * v3 * (1.f + erff(v3 * 0.70710678118654752f));
            }
            *(float2*)(Cz + (size_t)r0 * ldc + col)       = make_float2(v0, v1);
            *(float2*)(Cz + (size_t)(r0 + 8) * ldc + col) = make_float2(v2, v3);
        }
    }
}

// ---------------- row LayerNorm ----------------
__global__ __launch_bounds__(256) void k_ln_row(const float* __restrict__ src,
                                                const float* __restrict__ g,
                                                const float* __restrict__ b,
                                                float* __restrict__ dst) {
    __shared__ float red[8];
    size_t row = blockIdx.x;
    int tid = threadIdx.x;
    float4 v = ((const float4*)src)[row * 256 + tid];
    float m = block_sum_256(v.x + v.y + v.z + v.w, red) * (1.f / 1024.f);
    float dx = v.x - m, dy = v.y - m, dz = v.z - m, dw = v.w - m;
    float var = block_sum_256(dx*dx + dy*dy + dz*dz + dw*dw, red) * (1.f / 1024.f);
    float rs = rsqrtf(var + 1e-5f);
    float4 gv = ((const float4*)g)[tid], bv = ((const float4*)b)[tid];
    float4 o;
    o.x = dx * rs * gv.x + bv.x; o.y = dy * rs * gv.y + bv.y;
    o.z = dz * rs * gv.z + bv.z; o.w = dw * rs * gv.w + bv.w;
    ((float4*)dst)[row * 256 + tid] = o;
}

__global__ __launch_bounds__(128) void k_qh(const float* __restrict__ chw, const float* __restrict__ chb,
                                            const float* __restrict__ tw, const float* __restrict__ tb) {
    int side = blockIdx.y;
    const float* W  = side ? tw : chw;
    const float* bb = side ? tb : chb;
    const float* q  = g_qln[side];
    __shared__ float qs[F_];
    int tid = threadIdx.x;
    for (int i = tid; i < F_; i += 128) qs[i] = q[i];
    __syncthreads();
    int j = blockIdx.x * 128 + tid;
    float a0 = 0.f, a1 = 0.f, a2 = 0.f, a3 = 0.f;
    for (int f = 0; f < F_; f += 4) {
        a0 = fmaf(qs[f], W[(size_t)f * C3F + j], a0);
        a1 = fmaf(qs[f + 1], W[(size_t)(f + 1) * C3F + j], a1);
        a2 = fmaf(qs[f + 2], W[(size_t)(f + 2) * C3F + j], a2);
        a3 = fmaf(qs[f + 3], W[(size_t)(f + 3) * C3F + j], a3);
    }
    g_qh[side][j] = a0 + a1 + a2 + a3 + bb[j];
}

__global__ __launch_bounds__(128) void k_fold(const float* __restrict__ chw, const float* __restrict__ chb,
                                              const float* __restrict__ tw, const float* __restrict__ tb) {
    int side = blockIdx.y, f = blockIdx.x, tid = threadIdx.x;
    const float* W  = side ? tw : chw;
    const float* qh = g_qh[side];
    __shared__ float wrow[F_];
    for (int i = tid; i < F_; i += 128) wrow[i] = W[(size_t)f * C3F + F_ + i];
    __syncthreads();
    int h = tid >> 3, i8 = tid & 7;
    float s = 0.f;
    #pragma unroll
    for (int d = 0; d < 8; d++) s += wrow[h * 64 + i8 * 8 + d] * qh[h * 64 + i8 * 8 + d];
    s += __shfl_down_sync(0xffffffffu, s, 4, 8);
    s += __shfl_down_sync(0xffffffffu, s, 2, 8);
    s += __shfl_down_sync(0xffffffffu, s, 1, 8);
    if (i8 == 0) g_wkeff[side][h * F_ + f] = s;
    if (f == 0 && tid < H_) {
        const float* bb = side ? tb : chb;
        float bs = 0.f;
        for (int d = 0; d < 64; d++) bs += bb[F_ + tid * 64 + d] * qh[tid * 64 + d];
        g_bkeff[side][tid] = bs;
    }
}

// ---------------- fused stage-1 ----------------
#define SMEM_MAIN ((D_ * F_ + H_ * F_ + 288 + 288) * 4)
__global__ __launch_bounds__(256) void k_main(const float* __restrict__ x) {
    extern __shared__ float sm[];
    float* xs = sm;
    float* wk = xs + D_ * F_;
    float* sc = wk + H_ * F_;
    float* attnT = sc + 288;
    int p = blockIdx.x, b = blockIdx.y, tid = threadIdx.x;
    int t = b * P_ + p;
    const float4* xg = (const float4*)x;
    #pragma unroll
    for (int k = 0; k < D_; k++)
        ((float4*)xs)[k * 256 + tid] = xg[((size_t)(b * D_ + k) * P_ + p) * 256 + tid];
    const float4* wg = (const float4*)g_wkeff[0];
    #pragma unroll
    for (int i = 0; i < 16; i++) ((float4*)wk)[tid + i * 256] = wg[tid + i * 256];
    __syncthreads();
    int w = tid >> 5, lane = tid & 31;
    for (int j = 0; j < 36; j++) {
        int pair = w + 8 * j;
        int h = pair / D_, k = pair % D_;
        const float4* xr = (const float4*)(xs + k * F_);
        const float4* wr = (const float4*)(wk + h * F_);
        float s = 0.f;
        #pragma unroll
        for (int i = 0; i < 8; i++) {
            float4 a = xr[lane + 32 * i], bv = wr[lane + 32 * i];
            s = fmaf(a.x, bv.x, s); s = fmaf(a.y, bv.y, s);
            s = fmaf(a.z, bv.z, s); s = fmaf(a.w, bv.w, s);
        }
        #pragma unroll
        for (int o = 16; o; o >>= 1) s += __shfl_xor_sync(0xffffffffu, s, o);
        if (lane == 0) sc[pair] = (s + g_bkeff[0][h]) * 0.125f;
    }
    __syncthreads();
    if (tid < H_) {
        int h = tid;
        float mx = -1e30f;
        #pragma unroll
        for (int k = 0; k < D_; k++) mx = fmaxf(mx, sc[h * D_ + k]);
        float e[D_], ss = 0.f;
        #pragma unroll
        for (int k = 0; k < D_; k++) { e[k] = expf(sc[h * D_ + k] - mx); ss += e[k]; }
        float inv = 1.f / ss;
        #pragma unroll
        for (int k = 0; k < D_; k++) attnT[k * H_ + h] = e[k] * inv;
    }
    __syncthreads();
    float4 acc[H_];
    #pragma unroll
    for (int h = 0; h < H_; h++) acc[h] = make_float4(0.f, 0.f, 0.f, 0.f);
    #pragma unroll
    for (int k = 0; k < D_; k++) {
        float4 xv = ((const float4*)xs)[k * 256 + tid];
        const float4* at = (const float4*)(attnT + k * H_);
        float4 q0 = at[0], q1 = at[1], q2 = at[2], q3 = at[3];
        float av[16] = { q0.x,q0.y,q0.z,q0.w,q1.x,q1.y,q1.z,q1.w,q2.x,q2.y,q2.z,q2.w,q3.x,q3.y,q3.z,q3.w };
        #pragma unroll
        for (int h = 0; h < H_; h++) {
            acc[h].x = fmaf(av[h], xv.x, acc[h].x); acc[h].y = fmaf(av[h], xv.y, acc[h].y);
            acc[h].z = fmaf(av[h], xv.z, acc[h].z); acc[h].w = fmaf(av[h], xv.w, acc[h].w);
        }
    }
    #pragma unroll
    for (int h = 0; h < H_; h++)
        ((float4*)g_mixed)[((size_t)h * T_ + t) * 256 + tid] = acc[h];
}

// ---------------- kv = ln(ln(z, cn), pnp) ----------------
__global__ __launch_bounds__(256) void k_lnln(const float* __restrict__ g1, const float* __restrict__ b1,
                                              const float* __restrict__ g2, const float* __restrict__ b2) {
    __shared__ float red[8];
    size_t row = blockIdx.x;
    int tid = threadIdx.x;
    float4 v = ((const float4*)g_z)[row * 256 + tid];
    float m = block_sum_256(v.x + v.y + v.z + v.w, red) * (1.f / 1024.f);
    float dx = v.x - m, dy = v.y - m, dz = v.z - m, dw = v.w - m;
    float var = block_sum_256(dx*dx + dy*dy + dz*dz + dw*dw, red) * (1.f / 1024.f);
    float rs = rsqrtf(var + 1e-5f);
    float4 g1v = ((const float4*)g1)[tid], b1v = ((const float4*)b1)[tid];
    float yx = dx * rs * g1v.x + b1v.x, yy = dy * rs * g1v.y + b1v.y;
    float yz = dz * rs * g1v.z + b1v.z, yw = dw * rs * g1v.w + b1v.w;
    float m2 = block_sum_256(yx + yy + yz + yw, red) * (1.f / 1024.f);
    float ex = yx - m2, ey = yy - m2, ez = yz - m2, ew = yw - m2;
    float var2 = block_sum_256(ex*ex + ey*ey + ez*ez + ew*ew, red) * (1.f / 1024.f);
    float rs2 = rsqrtf(var2 + 1e-5f);
    float4 g2v = ((const float4*)g2)[tid], b2v = ((const float4*)b2)[tid];
    float4 o;
    o.x = ex * rs2 * g2v.x + b2v.x; o.y = ey * rs2 * g2v.y + b2v.y;
    o.z = ez * rs2 * g2v.z + b2v.z; o.w = ew * rs2 * g2v.w + b2v.w;
    ((float4*)g_kv)[row * 256 + tid] = o;
}

// ---------------- stage-2 fused ----------------
__global__ __launch_bounds__(256) void k_sc2mix() {
    __shared__ float sc[H_ * P_];
    int b = blockIdx.x, tid = threadIdx.x, w = tid >> 5, lane = tid & 31;
    for (int j = 0; j < 128; j++) {
        int pair = w + 8 * j;
        int h = pair >> 6, p = pair & 63;
        const float4* kr = (const float4*)(g_kv + (size_t)(b * P_ + p) * F_);
        const float4* wr = (const float4*)(g_wkeff[1] + h * F_);
        float s = 0.f;
        #pragma unroll
        for (int i = 0; i < 8; i++) {
            float4 a = kr[lane + 32 * i], bv = wr[lane + 32 * i];
            s = fmaf(a.x, bv.x, s); s = fmaf(a.y, bv.y, s);
            s = fmaf(a.z, bv.z, s); s = fmaf(a.w, bv.w, s);
        }
        #pragma unroll
        for (int o = 16; o; o >>= 1) s += __shfl_xor_sync(0xffffffffu, s, o);
        if (lane == 0) sc[h * P_ + p] = (s + g_bkeff[1][h]) * 0.125f;
    }
    __syncthreads();
    if (tid < H_) {
        int h = tid;
        float mx = -1e30f;
        for (int p = 0; p < P_; p++) mx = fmaxf(mx, sc[h * P_ + p]);
        float ss = 0.f;
        for (int p = 0; p < P_; p++) { float e = expf(sc[h * P_ + p] - mx); sc[h * P_ + p] = e; ss += e; }
        float inv = 1.f / ss;
        for (int p = 0; p < P_; p++) sc[h * P_ + p] *= inv;
    }
    __syncthreads();
    float4 acc[H_];
    #pragma unroll
    for (int h = 0; h < H_; h++) acc[h] = make_float4(0.f, 0.f, 0.f, 0.f);
    for (int p = 0; p < P_; p++) {
        float4 xv = ((const float4*)g_kv)[(size_t)(b * P_ + p) * 256 + tid];
        #pragma unroll
        for (int h = 0; h < H_; h++) {
            float a = sc[h * P_ + p];
            acc[h].x = fmaf(a, xv.x, acc[h].x); acc[h].y = fmaf(a, xv.y, acc[h].y);
            acc[h].z = fmaf(a, xv.z, acc[h].z); acc[h].w = fmaf(a, xv.w, acc[h].w);
        }
    }
    #pragma unroll
    for (int h = 0; h < H_; h++)
        ((float4*)g_mixed2)[(size_t)(h * B_ + b) * 256 + tid] = acc[h];
}

__global__ __launch_bounds__(256) void k_logits(const float* __restrict__ w2,
                                                const float* __restrict__ b2,
                                                float* __restrict__ out) {
    int b = blockIdx.x, tid = threadIdx.x, w = tid >> 5, lane = tid & 31;
    const float* hrow = g_hid + (size_t)b * MH;
    for (int c = w; c < NC; c += 8) {
        float s = 0.f;
        for (int i = lane; i < MH; i += 32) s = fmaf(hrow[i], w2[(size_t)i * NC + c], s);
        #pragma unroll
        for (int o = 16; o; o >>= 1) s += __shfl_xor_sync(0xffffffffu, s, o);
        if (lane == 0) out[b * NC + c] = s + b2[c];
    }
}

// ---------------- launch ----------------
extern "C" void kernel_launch(void* const* d_in, const int* in_sizes, int n_in,
                              void* d_out, int out_size) {
    (void)in_sizes; (void)n_in; (void)out_size;
    const float* x    = (const float*)d_in[0];
    const float* chq  = (const float*)d_in[1];
    const float* clq  = (const float*)d_in[2];
    const float* chw  = (const float*)d_in[3];
    const float* chb  = (const float*)d_in[4];
    const float* chow = (const float*)d_in[5];
    const float* chob = (const float*)d_in[6];
    const float* tw   = (const float*)d_in[7];
    const float* tb   = (const float*)d_in[8];
    const float* tow  = (const float*)d_in[9];
    const float* tob  = (const float*)d_in[10];
    const float* qn_g = (const float*)d_in[11];
    const float* qn_b = (const float*)d_in[12];
    const float* cn_g = (const float*)d_in[13];
    const float* cn_b = (const float*)d_in[14];
    const float* pnc_g = (const float*)d_in[15];
    const float* pnc_b = (const float*)d_in[16];
    const float* pnp_g = (const float*)d_in[17];
    const float* pnp_b = (const float*)d_in[18];
    const float* pon_g = (const float*)d_in[19];
    const float* pon_b = (const float*)d_in[20];
    const float* w1 = (const float*)d_in[21];
    const float* b1 = (const float*)d_in[22];
    const float* w2 = (const float*)d_in[23];
    const float* b2 = (const float*)d_in[24];
    float* out = (float*)d_out;

    float *p_qln, *p_mixed, *p_pooled, *p_z, *p_mixed2, *p_pooled2, *p_p2, *p_p2ln, *p_hid;
    __nv_bfloat16 *wvh, *wvl, *cwh, *cwl, *w2h, *w2l, *toh, *tol, *w1h, *w1l;
    cudaGetSymbolAddress((void**)&p_qln, g_qln);
    cudaGetSymbolAddress((void**)&p_mixed, g_mixed);
    cudaGetSymbolAddress((void**)&p_pooled, g_pooled);
    cudaGetSymbolAddress((void**)&p_z, g_z);
    cudaGetSymbolAddress((void**)&p_mixed2, g_mixed2);
    cudaGetSymbolAddress((void**)&p_pooled2, g_pooled2);
    cudaGetSymbolAddress((void**)&p_p2, g_p2);
    cudaGetSymbolAddress((void**)&p_p2ln, g_p2ln);
    cudaGetSymbolAddress((void**)&p_hid, g_hid);
    cudaGetSymbolAddress((void**)&wvh, g_wvT_h);  cudaGetSymbolAddress((void**)&wvl, g_wvT_l);
    cudaGetSymbolAddress((void**)&cwh, g_chowT_h); cudaGetSymbolAddress((void**)&cwl, g_chowT_l);
    cudaGetSymbolAddress((void**)&w2h, g_wv2T_h); cudaGetSymbolAddress((void**)&w2l, g_wv2T_l);
    cudaGetSymbolAddress((void**)&toh, g_towT_h); cudaGetSymbolAddress((void**)&tol, g_towT_l);
    cudaGetSymbolAddress((void**)&w1h, g_w1T_h);  cudaGetSymbolAddress((void**)&w1l, g_w1T_l);

    cudaFuncSetAttribute(k_main, cudaFuncAttributeMaxDynamicSharedMemorySize, SMEM_MAIN);

    // weight prep
    k_trsplit<<<dim3(32, 32), 256>>>(chw, C3F, 2 * F_, wvh, wvl);
    k_trsplit<<<dim3(32, 32), 256>>>(chow, F_, 0, cwh, cwl);
    k_trsplit<<<dim3(32, 32), 256>>>(tw, C3F, 2 * F_, w2h, w2l);
    k_trsplit<<<dim3(32, 32), 256>>>(tow, F_, 0, toh, tol);
    k_trsplit<<<dim3(32, 128), 256>>>(w1, MH, 0, w1h, w1l);

    k_ln_row<<<1, 256>>>(chq, qn_g, qn_b, p_qln);
    k_ln_row<<<1, 256>>>(clq, pnc_g, pnc_b, p_qln + F_);
    k_qh<<<dim3(8, 2), 128>>>(chw, chb, tw, tb);
    k_fold<<<dim3(1024, 2), 128>>>(chw, chb, tw, tb);
    k_main<<<dim3(P_, B_), 256, SMEM_MAIN>>>(x);
    // pooled = mixed_h @ Wv_h + bv  (batched over 16 heads)
    k_mma<<<dim3(1, T_ / 128, H_), 256>>>(p_mixed, F_, (long long)T_ * F_,
        wvh, wvl, (long long)64 * F_, chb + 2 * F_, 64, p_pooled, F_, 64, 0);
    // z = pooled @ chow + chob
    k_mma<<<dim3(F_ / 64, T_ / 128, 1), 256>>>(p_pooled, F_, 0,
        cwh, cwl, 0, chob, 0, p_z, F_, 0, 0);
    k_lnln<<<T_, 256>>>(cn_g, cn_b, pnp_g, pnp_b);
    k_sc2mix<<<B_, 256>>>();
    // pooled2 = mixed2_h @ Wv2_h + bv2
    k_mma<<<dim3(1, 1, H_), 256>>>(p_mixed2, F_, (long long)B_ * F_,
        w2h, w2l, (long long)64 * F_, tb + 2 * F_, 64, p_pooled2, F_, 64, 0);
    // p2 = pooled2 @ tow + tob
    k_mma<<<dim3(F_ / 64, 1, 1), 256>>>(p_pooled2, F_, 0,
        toh, tol, 0, tob, 0, p_p2, F_, 0, 0);
    k_ln_row<<<B_, 256>>>(p_p2, pon_g, pon_b, p_p2ln);
    // hid = gelu(p2ln @ w1 + b1)
    k_mma<<<dim3(MH / 64, 1, 1), 256>>>(p_p2ln, F_, 0,
        w1h, w1l, 0, b1, 0, p_hid, MH, 0, 1);
    k_logits<<<B_, 256>>>(w2, b2, out);
}

// round 9
// speedup vs baseline: 1.8611x; 1.5668x over previous
#include <cuda_runtime.h>
#include <cuda_bf16.h>
#include <math.h>
#include <stdint.h>

#define F_  1024
#define H_  16
#define D_  18
#define P_  64
#define B_  128
#define T_  8192
#define C3F 3072
#define NC  23
#define MH  4096

typedef __nv_bfloat16 bf16;

__device__ float g_qln[2][F_];
__device__ float g_qh[2][F_];
__device__ float g_wkeff[2][H_ * F_];
__device__ float g_bkeff[2][H_];
__device__ float g_z[(size_t)T_ * F_];
__device__ float g_kv[(size_t)T_ * F_];
__device__ float g_p2[B_ * F_];
__device__ float g_hid[B_ * MH];
// bf16 hi/lo activation planes
__device__ __align__(16) bf16 g_mx_h[(size_t)H_ * T_ * F_], g_mx_l[(size_t)H_ * T_ * F_];
__device__ __align__(16) bf16 g_pooled_h[(size_t)T_ * F_], g_pooled_l[(size_t)T_ * F_];
__device__ __align__(16) bf16 g_mx2_h[H_ * B_ * F_], g_mx2_l[H_ * B_ * F_];
__device__ __align__(16) bf16 g_pooled2_h[B_ * F_], g_pooled2_l[B_ * F_];
__device__ __align__(16) bf16 g_p2ln_h[B_ * F_], g_p2ln_l[B_ * F_];
// bf16 hi/lo weight planes (transposed, [N][1024])
__device__ __align__(16) bf16 g_wvT_h[F_ * F_],  g_wvT_l[F_ * F_];
__device__ __align__(16) bf16 g_chowT_h[F_ * F_], g_chowT_l[F_ * F_];
__device__ __align__(16) bf16 g_wv2T_h[F_ * F_], g_wv2T_l[F_ * F_];
__device__ __align__(16) bf16 g_towT_h[F_ * F_], g_towT_l[F_ * F_];
__device__ __align__(16) bf16 g_w1T_h[MH * F_],  g_w1T_l[MH * F_];

__device__ __forceinline__ uint32_t smem_u32(const void* p) {
    uint32_t a;
    asm("{ .reg .u64 t; cvta.to.shared.u64 t, %1; cvt.u32.u64 %0, t; }" : "=r"(a) : "l"(p));
    return a;
}
__device__ __forceinline__ void ldsm4(uint32_t& r0, uint32_t& r1, uint32_t& r2, uint32_t& r3, uint32_t a) {
    asm volatile("ldmatrix.sync.aligned.m8n8.x4.shared.b16 {%0,%1,%2,%3}, [%4];"
        : "=r"(r0), "=r"(r1), "=r"(r2), "=r"(r3) : "r"(a));
}
__device__ __forceinline__ void mma_bf16(float* c, const uint32_t* a, uint32_t b0, uint32_t b1) {
    asm volatile("mma.sync.aligned.m16n8k16.row.col.f32.bf16.bf16.f32 "
        "{%0,%1,%2,%3},{%4,%5,%6,%7},{%8,%9},{%0,%1,%2,%3};"
        : "+f"(c[0]), "+f"(c[1]), "+f"(c[2]), "+f"(c[3])
        : "r"(a[0]), "r"(a[1]), "r"(a[2]), "r"(a[3]), "r"(b0), "r"(b1));
}
#define CP16(dst, src) asm volatile("cp.async.cg.shared.global [%0], [%1], 16;" :: "r"(dst), "l"(src))
#define CPCOMMIT()     asm volatile("cp.async.commit_group;" ::: "memory")
#define CPWAIT(n)      asm volatile("cp.async.wait_group %0;" :: "n"(n) : "memory")

__device__ __forceinline__ void sp2(float v0, float v1, uint32_t& h, uint32_t& l) {
    bf16 h0 = __float2bfloat16(v0), h1 = __float2bfloat16(v1);
    bf16 l0 = __float2bfloat16(v0 - __bfloat162float(h0));
    bf16 l1 = __float2bfloat16(v1 - __bfloat162float(h1));
    h = ((uint32_t)__bfloat16_as_ushort(h1) << 16) | __bfloat16_as_ushort(h0);
    l = ((uint32_t)__bfloat16_as_ushort(l1) << 16) | __bfloat16_as_ushort(l0);
}
__device__ __forceinline__ float block_sum_256(float v, float* red) {
    #pragma unroll
    for (int o = 16; o; o >>= 1) v += __shfl_xor_sync(0xffffffffu, v, o);
    int w = threadIdx.x >> 5;
    if ((threadIdx.x & 31) == 0) red[w] = v;
    __syncthreads();
    float s = red[0];
    #pragma unroll
    for (int i = 1; i < 8; i++) s += red[i];
    __syncthreads();
    return s;
}

// ---------------- weight transpose + split ----------------
__global__ __launch_bounds__(256) void k_trsplit(const float* __restrict__ src, int lds, int ofs,
                                                 bf16* __restrict__ dh, bf16* __restrict__ dl) {
    __shared__ float t[32][33];
    int k0 = blockIdx.x * 32, n0 = blockIdx.y * 32;
    int tx = threadIdx.x & 31, ty = threadIdx.x >> 5;
    #pragma unroll
    for (int j = 0; j < 4; j++)
        t[ty + j * 8][tx] = src[(size_t)(k0 + ty + j * 8) * lds + ofs + n0 + tx];
    __syncthreads();
    #pragma unroll
    for (int j = 0; j < 4; j++) {
        int r = ty + j * 8;
        float v = t[tx][r];
        bf16 h = __float2bfloat16(v);
        bf16 l = __float2bfloat16(v - __bfloat162float(h));
        size_t o = (size_t)(n0 + r) * F_ + k0 + tx;
        dh[o] = h; dl[o] = l;
    }
}

// ---------------- cp.async 3-stage split-bf16 GEMM ----------------
// C[128 x 64-tile] = A @ B^T (+bias). A,B given as bf16 hi/lo planes [rows][1024].
// mode: 0 = f32 out, 1 = f32 gelu out, 2 = bf16 hi/lo plane out.
#define STG_B 18432      // per-stage bytes: Ah 6144 | Al 6144 | Bh 3072 | Bl 3072
__global__ __launch_bounds__(256) void k_mma(
    const bf16* __restrict__ Ah, const bf16* __restrict__ Al, long long sA,
    const bf16* __restrict__ Bh, const bf16* __restrict__ Bl, long long sB,
    const float* __restrict__ bias, long long sBias,
    float* __restrict__ Cf, bf16* __restrict__ Ch, bf16* __restrict__ Cl,
    int ldc, long long sC, int mode)
{
    extern __shared__ bf16 s[];
    int z = blockIdx.z;
    Ah += (size_t)z * sA; Al += (size_t)z * sA;
    Bh += (size_t)z * sB; Bl += (size_t)z * sB;
    const float* bz = bias + (size_t)z * sBias;
    const int tM = blockIdx.y * 128, tN = blockIdx.x * 64;
    const int t = threadIdx.x, wid = t >> 5, lane = t & 31;
    const int m_idx = wid >> 1, n_idx = wid & 1;
    uint32_t sbase = smem_u32(s);

    // cp.async per-thread sources/dests
    const int ar = t >> 1, aseg = t & 1;
    const bf16* agh = Ah + (size_t)(tM + ar) * F_ + aseg * 8;
    const bf16* agl = Al + (size_t)(tM + ar) * F_ + aseg * 8;
    const uint32_t adst = ar * 48 + aseg * 16;
    const int br = (t & 127) >> 1, bseg = t & 1;
    const bf16* bgp = ((t < 128) ? Bh : Bl) + (size_t)(tN + br) * F_ + bseg * 8;
    const uint32_t bdst = 12288 + ((t >= 128) ? 3072u : 0u) + br * 48 + bseg * 16;

    // ldmatrix offsets (within stage)
    uint32_t oA[2], oB[2];
    #pragma unroll
    for (int ti = 0; ti < 2; ti++) {
        int r = m_idx * 32 + ti * 16 + (lane & 15);
        oA[ti] = r * 48 + (lane >> 4) * 16;
    }
    #pragma unroll
    for (int gi = 0; gi < 2; gi++) {
        int mtx = lane >> 3;
        int nr = n_idx * 32 + gi * 16 + (mtx >> 1) * 8 + (lane & 7);
        oB[gi] = 12288 + nr * 48 + (mtx & 1) * 16;
    }

    float acc[2][4][4];
    #pragma unroll
    for (int i = 0; i < 2; i++)
        #pragma unroll
        for (int j = 0; j < 4; j++)
            #pragma unroll
            for (int k = 0; k < 4; k++) acc[i][j][k] = 0.f;

    // prologue: stages for chunks 0,1
    #pragma unroll
    for (int sp = 0; sp < 2; sp++) {
        uint32_t sb = sbase + sp * STG_B;
        CP16(sb + adst, agh + sp * 16);
        CP16(sb + 6144 + adst, agl + sp * 16);
        CP16(sb + bdst, bgp + sp * 16);
        CPCOMMIT();
    }

    for (int c = 0; c < 64; c++) {
        if (c < 62) {
            int nc = c + 2;
            uint32_t sb = sbase + (nc % 3) * STG_B;
            CP16(sb + adst, agh + nc * 16);
            CP16(sb + 6144 + adst, agl + nc * 16);
            CP16(sb + bdst, bgp + nc * 16);
            CPCOMMIT();
            CPWAIT(2);
        } else if (c == 62) CPWAIT(1);
        else CPWAIT(0);
        __syncthreads();

        uint32_t sb = sbase + (c % 3) * STG_B;
        uint32_t Ahf[2][4], Alf[2][4], Bhf[2][4], Blf[2][4];
        #pragma unroll
        for (int ti = 0; ti < 2; ti++) {
            ldsm4(Ahf[ti][0], Ahf[ti][1], Ahf[ti][2], Ahf[ti][3], sb + oA[ti]);
            ldsm4(Alf[ti][0], Alf[ti][1], Alf[ti][2], Alf[ti][3], sb + 6144 + oA[ti]);
        }
        #pragma unroll
        for (int gi = 0; gi < 2; gi++) {
            ldsm4(Bhf[gi][0], Bhf[gi][1], Bhf[gi][2], Bhf[gi][3], sb + oB[gi]);
            ldsm4(Blf[gi][0], Blf[gi][1], Blf[gi][2], Blf[gi][3], sb + 3072 + oB[gi]);
        }
        #pragma unroll
        for (int ti = 0; ti < 2; ti++)
            #pragma unroll
            for (int gi = 0; gi < 2; gi++)
                #pragma unroll
                for (int sub = 0; sub < 2; sub++) {
                    int tn = gi * 2 + sub;
                    mma_bf16(acc[ti][tn], Ahf[ti], Bhf[gi][2 * sub], Bhf[gi][2 * sub + 1]);
                    mma_bf16(acc[ti][tn], Ahf[ti], Blf[gi][2 * sub], Blf[gi][2 * sub + 1]);
                    mma_bf16(acc[ti][tn], Alf[ti], Bhf[gi][2 * sub], Bhf[gi][2 * sub + 1]);
                }
        __syncthreads();
    }

    const int g = lane >> 2, tg = lane & 3;
    #pragma unroll
    for (int ti = 0; ti < 2; ti++) {
        int r0 = tM + m_idx * 32 + ti * 16 + g;
        #pragma unroll
        for (int tn = 0; tn < 4; tn++) {
            int col = tN + n_idx * 32 + tn * 8 + tg * 2;
            float b0 = bz[col], b1 = bz[col + 1];
            float v0 = acc[ti][tn][0] + b0, v1 = acc[ti][tn][1] + b1;
            float v2 = acc[ti][tn][2] + b0, v3 = acc[ti][tn][3] + b1;
            if (mode == 1) {
                v0 = 0.5f * v0 * (1.f + erff(v0 * 0.70710678118654752f));
                v1 = 0.5f * v1 * (1.f + erff(v1 * 0.70710678118654752f));
                v2 = 0.5f * v2 * (1.f + erff(v2 * 0.70710678118654752f));
                v3 = 0.5f * v3 * (1.f + erff(v3 * 0.70710678118654752f));
            }
            if (mode == 2) {
                uint32_t h, l;
                sp2(v0, v1, h, l);
                *(uint32_t*)(Ch + (size_t)z * sC + (size_t)r0 * ldc + col) = h;
                *(uint32_t*)(Cl + (size_t)z * sC + (size_t)r0 * ldc + col) = l;
                sp2(v2, v3, h, l);
                *(uint32_t*)(Ch + (size_t)z * sC + (size_t)(r0 + 8) * ldc + col) = h;
                *(uint32_t*)(Cl + (size_t)z * sC + (size_t)(r0 + 8) * ldc + col) = l;
            } else {
                float* Cz = Cf + (size_t)z * sC;
                *(float2*)(Cz + (size_t)r0 * ldc + col)       = make_float2(v0, v1);
                *(float2*)(Cz + (size_t)(r0 + 8) * ldc + col) = make_float2(v2, v3);
            }
        }
    }
}

// ---------------- row LayerNorm (f32 out) ----------------
__global__ __launch_bounds__(256) void k_ln_row(const float* __restrict__ src,
                                                const float* __restrict__ g,
                                                const float* __restrict__ b,
                                                float* __restrict__ dst) {
    __shared__ float red[8];
    size_t row = blockIdx.x;
    int tid = threadIdx.x;
    float4 v = ((const float4*)src)[row * 256 + tid];
    float m = block_sum_256(v.x + v.y + v.z + v.w, red) * (1.f / 1024.f);
    float dx = v.x - m, dy = v.y - m, dz = v.z - m, dw = v.w - m;
    float var = block_sum_256(dx*dx + dy*dy + dz*dz + dw*dw, red) * (1.f / 1024.f);
    float rs = rsqrtf(var + 1e-5f);
    float4 gv = ((const float4*)g)[tid], bv = ((const float4*)b)[tid];
    float4 o;
    o.x = dx * rs * gv.x + bv.x; o.y = dy * rs * gv.y + bv.y;
    o.z = dz * rs * gv.z + bv.z; o.w = dw * rs * gv.w + bv.w;
    ((float4*)dst)[row * 256 + tid] = o;
}

// ---------------- row LayerNorm (bf16 hi/lo plane out) ----------------
__global__ __launch_bounds__(256) void k_ln_split(const float* __restrict__ src,
                                                  const float* __restrict__ g,
                                                  const float* __restrict__ b,
                                                  bf16* __restrict__ dh, bf16* __restrict__ dl) {
    __shared__ float red[8];
    size_t row = blockIdx.x;
    int tid = threadIdx.x;
    float4 v = ((const float4*)src)[row * 256 + tid];
    float m = block_sum_256(v.x + v.y + v.z + v.w, red) * (1.f / 1024.f);
    float dx = v.x - m, dy = v.y - m, dz = v.z - m, dw = v.w - m;
    float var = block_sum_256(dx*dx + dy*dy + dz*dz + dw*dw, red) * (1.f / 1024.f);
    float rs = rsqrtf(var + 1e-5f);
    float4 gv = ((const float4*)g)[tid], bv = ((const float4*)b)[tid];
    float o0 = dx * rs * gv.x + bv.x, o1 = dy * rs * gv.y + bv.y;
    float o2 = dz * rs * gv.z + bv.z, o3 = dw * rs * gv.w + bv.w;
    uint2 uh, ul;
    sp2(o0, o1, uh.x, ul.x);
    sp2(o2, o3, uh.y, ul.y);
    ((uint2*)dh)[row * 256 + tid] = uh;
    ((uint2*)dl)[row * 256 + tid] = ul;
}

__global__ __launch_bounds__(128) void k_qh(const float* __restrict__ chw, const float* __restrict__ chb,
                                            const float* __restrict__ tw, const float* __restrict__ tb) {
    int side = blockIdx.y;
    const float* W  = side ? tw : chw;
    const float* bb = side ? tb : chb;
    const float* q  = g_qln[side];
    __shared__ float qs[F_];
    int tid = threadIdx.x;
    for (int i = tid; i < F_; i += 128) qs[i] = q[i];
    __syncthreads();
    int j = blockIdx.x * 128 + tid;
    float a0 = 0.f, a1 = 0.f, a2 = 0.f, a3 = 0.f;
    for (int f = 0; f < F_; f += 4) {
        a0 = fmaf(qs[f], W[(size_t)f * C3F + j], a0);
        a1 = fmaf(qs[f + 1], W[(size_t)(f + 1) * C3F + j], a1);
        a2 = fmaf(qs[f + 2], W[(size_t)(f + 2) * C3F + j], a2);
        a3 = fmaf(qs[f + 3], W[(size_t)(f + 3) * C3F + j], a3);
    }
    g_qh[side][j] = a0 + a1 + a2 + a3 + bb[j];
}

__global__ __launch_bounds__(128) void k_fold(const float* __restrict__ chw, const float* __restrict__ chb,
                                              const float* __restrict__ tw, const float* __restrict__ tb) {
    int side = blockIdx.y, f = blockIdx.x, tid = threadIdx.x;
    const float* W  = side ? tw : chw;
    const float* qh = g_qh[side];
    __shared__ float wrow[F_];
    for (int i = tid; i < F_; i += 128) wrow[i] = W[(size_t)f * C3F + F_ + i];
    __syncthreads();
    int h = tid >> 3, i8 = tid & 7;
    float s = 0.f;
    #pragma unroll
    for (int d = 0; d < 8; d++) s += wrow[h * 64 + i8 * 8 + d] * qh[h * 64 + i8 * 8 + d];
    s += __shfl_down_sync(0xffffffffu, s, 4, 8);
    s += __shfl_down_sync(0xffffffffu, s, 2, 8);
    s += __shfl_down_sync(0xffffffffu, s, 1, 8);
    if (i8 == 0) g_wkeff[side][h * F_ + f] = s;
    if (f == 0 && tid < H_) {
        const float* bb = side ? tb : chb;
        float bs = 0.f;
        for (int d = 0; d < 64; d++) bs += bb[F_ + tid * 64 + d] * qh[tid * 64 + d];
        g_bkeff[side][tid] = bs;
    }
}

// ---------------- fused stage-1: warp-per-2-heads scores, softmax(D), mix -> hi/lo ----------------
#define SMEM_MAIN ((D_ * F_ + 288 + 288) * 4)
__global__ __launch_bounds__(256) void k_main(const float* __restrict__ x) {
    extern __shared__ float sm[];
    float* xs = sm;
    float* sc = xs + D_ * F_;          // [h*18+k]
    float* attnT = sc + 288;           // [k*16+h]
    int p = blockIdx.x, b = blockIdx.y, tid = threadIdx.x;
    int t = b * P_ + p;
    int w = tid >> 5, lane = tid & 31;

    // wk rows for this warp's two heads -> registers (from L2)
    int h0 = 2 * w, h1 = 2 * w + 1;
    float4 wk0[8], wk1[8];
    const float4* wg0 = (const float4*)(g_wkeff[0] + h0 * F_);
    const float4* wg1 = (const float4*)(g_wkeff[0] + h1 * F_);
    #pragma unroll
    for (int i = 0; i < 8; i++) { wk0[i] = wg0[lane + 32 * i]; wk1[i] = wg1[lane + 32 * i]; }
    float bk0 = g_bkeff[0][h0], bk1 = g_bkeff[0][h1];

    const float4* xg = (const float4*)x;
    #pragma unroll
    for (int k = 0; k < D_; k++)
        ((float4*)xs)[k * 256 + tid] = xg[((size_t)(b * D_ + k) * P_ + p) * 256 + tid];
    __syncthreads();

    // scores: warp w computes heads h0,h1 over all k
    for (int k = 0; k < D_; k++) {
        const float4* xr = (const float4*)(xs + k * F_);
        float s0 = 0.f, s1 = 0.f;
        #pragma unroll
        for (int i = 0; i < 8; i++) {
            float4 a = xr[lane + 32 * i];
            s0 = fmaf(a.x, wk0[i].x, s0); s0 = fmaf(a.y, wk0[i].y, s0);
            s0 = fmaf(a.z, wk0[i].z, s0); s0 = fmaf(a.w, wk0[i].w, s0);
            s1 = fmaf(a.x, wk1[i].x, s1); s1 = fmaf(a.y, wk1[i].y, s1);
            s1 = fmaf(a.z, wk1[i].z, s1); s1 = fmaf(a.w, wk1[i].w, s1);
        }
        #pragma unroll
        for (int o = 16; o; o >>= 1) {
            s0 += __shfl_xor_sync(0xffffffffu, s0, o);
            s1 += __shfl_xor_sync(0xffffffffu, s1, o);
        }
        if (lane == 0) {
            sc[h0 * D_ + k] = (s0 + bk0) * 0.125f;
            sc[h1 * D_ + k] = (s1 + bk1) * 0.125f;
        }
    }
    __syncthreads();

    if (tid < H_) {
        int h = tid;
        float mx = -1e30f;
        #pragma unroll
        for (int k = 0; k < D_; k++) mx = fmaxf(mx, sc[h * D_ + k]);
        float e[D_], ss = 0.f;
        #pragma unroll
        for (int k = 0; k < D_; k++) { e[k] = expf(sc[h * D_ + k] - mx); ss += e[k]; }
        float inv = 1.f / ss;
        #pragma unroll
        for (int k = 0; k < D_; k++) attnT[k * H_ + tid] = e[k] * inv;
    }
    __syncthreads();

    float4 acc[H_];
    #pragma unroll
    for (int h = 0; h < H_; h++) acc[h] = make_float4(0.f, 0.f, 0.f, 0.f);
    #pragma unroll
    for (int k = 0; k < D_; k++) {
        float4 xv = ((const float4*)xs)[k * 256 + tid];
        const float4* at = (const float4*)(attnT + k * H_);
        float4 q0 = at[0], q1 = at[1], q2 = at[2], q3 = at[3];
        float av[16] = { q0.x,q0.y,q0.z,q0.w,q1.x,q1.y,q1.z,q1.w,q2.x,q2.y,q2.z,q2.w,q3.x,q3.y,q3.z,q3.w };
        #pragma unroll
        for (int h = 0; h < H_; h++) {
            acc[h].x = fmaf(av[h], xv.x, acc[h].x); acc[h].y = fmaf(av[h], xv.y, acc[h].y);
            acc[h].z = fmaf(av[h], xv.z, acc[h].z); acc[h].w = fmaf(av[h], xv.w, acc[h].w);
        }
    }
    #pragma unroll
    for (int h = 0; h < H_; h++) {
        uint2 uh, ul;
        sp2(acc[h].x, acc[h].y, uh.x, ul.x);
        sp2(acc[h].z, acc[h].w, uh.y, ul.y);
        size_t o = ((size_t)h * T_ + t) * 256 + tid;
        ((uint2*)g_mx_h)[o] = uh;
        ((uint2*)g_mx_l)[o] = ul;
    }
}

// ---------------- kv = ln(ln(z, cn), pnp) ----------------
__global__ __launch_bounds__(256) void k_lnln(const float* __restrict__ g1, const float* __restrict__ b1,
                                              const float* __restrict__ g2, const float* __restrict__ b2) {
    __shared__ float red[8];
    size_t row = blockIdx.x;
    int tid = threadIdx.x;
    float4 v = ((const float4*)g_z)[row * 256 + tid];
    float m = block_sum_256(v.x + v.y + v.z + v.w, red) * (1.f / 1024.f);
    float dx = v.x - m, dy = v.y - m, dz = v.z - m, dw = v.w - m;
    float var = block_sum_256(dx*dx + dy*dy + dz*dz + dw*dw, red) * (1.f / 1024.f);
    float rs = rsqrtf(var + 1e-5f);
    float4 g1v = ((const float4*)g1)[tid], b1v = ((const float4*)b1)[tid];
    float yx = dx * rs * g1v.x + b1v.x, yy = dy * rs * g1v.y + b1v.y;
    float yz = dz * rs * g1v.z + b1v.z, yw = dw * rs * g1v.w + b1v.w;
    float m2 = block_sum_256(yx + yy + yz + yw, red) * (1.f / 1024.f);
    float ex = yx - m2, ey = yy - m2, ez = yz - m2, ew = yw - m2;
    float var2 = block_sum_256(ex*ex + ey*ey + ez*ez + ew*ew, red) * (1.f / 1024.f);
    float rs2 = rsqrtf(var2 + 1e-5f);
    float4 g2v = ((const float4*)g2)[tid], b2v = ((const float4*)b2)[tid];
    float4 o;
    o.x = ex * rs2 * g2v.x + b2v.x; o.y = ey * rs2 * g2v.y + b2v.y;
    o.z = ez * rs2 * g2v.z + b2v.z; o.w = ew * rs2 * g2v.w + b2v.w;
    ((float4*)g_kv)[row * 256 + tid] = o;
}

// ---------------- stage-2 fused ----------------
__global__ __launch_bounds__(256) void k_sc2mix() {
    __shared__ float sc[H_ * P_];
    int b = blockIdx.x, tid = threadIdx.x, w = tid >> 5, lane = tid & 31;
    for (int j = 0; j < 128; j++) {
        int pair = w + 8 * j;
        int h = pair >> 6, p = pair & 63;
        const float4* kr = (const float4*)(g_kv + (size_t)(b * P_ + p) * F_);
        const float4* wr = (const float4*)(g_wkeff[1] + h * F_);
        float s = 0.f;
        #pragma unroll
        for (int i = 0; i < 8; i++) {
            float4 a = kr[lane + 32 * i], bv = wr[lane + 32 * i];
            s = fmaf(a.x, bv.x, s); s = fmaf(a.y, bv.y, s);
            s = fmaf(a.z, bv.z, s); s = fmaf(a.w, bv.w, s);
        }
        #pragma unroll
        for (int o = 16; o; o >>= 1) s += __shfl_xor_sync(0xffffffffu, s, o);
        if (lane == 0) sc[h * P_ + p] = (s + g_bkeff[1][h]) * 0.125f;
    }
    __syncthreads();
    if (tid < H_) {
        int h = tid;
        float mx = -1e30f;
        for (int p = 0; p < P_; p++) mx = fmaxf(mx, sc[h * P_ + p]);
        float ss = 0.f;
        for (int p = 0; p < P_; p++) { float e = expf(sc[h * P_ + p] - mx); sc[h * P_ + p] = e; ss += e; }
        float inv = 1.f / ss;
        for (int p = 0; p < P_; p++) sc[h * P_ + p] *= inv;
    }
    __syncthreads();
    float4 acc[H_];
    #pragma unroll
    for (int h = 0; h < H_; h++) acc[h] = make_float4(0.f, 0.f, 0.f, 0.f);
    for (int p = 0; p < P_; p++) {
        float4 xv = ((const float4*)g_kv)[(size_t)(b * P_ + p) * 256 + tid];
        #pragma unroll
        for (int h = 0; h < H_; h++) {
            float a = sc[h * P_ + p];
            acc[h].x = fmaf(a, xv.x, acc[h].x); acc[h].y = fmaf(a, xv.y, acc[h].y);
            acc[h].z = fmaf(a, xv.z, acc[h].z); acc[h].w = fmaf(a, xv.w, acc[h].w);
        }
    }
    #pragma unroll
    for (int h = 0; h < H_; h++) {
        uint2 uh, ul;
        sp2(acc[h].x, acc[h].y, uh.x, ul.x);
        sp2(acc[h].z, acc[h].w, uh.y, ul.y);
        size_t o = (size_t)(h * B_ + b) * 256 + tid;
        ((uint2*)g_mx2_h)[o] = uh;
        ((uint2*)g_mx2_l)[o] = ul;
    }
}

__global__ __launch_bounds__(256) void k_logits(const float* __restrict__ w2,
                                                const float* __restrict__ b2,
                                                float* __restrict__ out) {
    int b = blockIdx.x, tid = threadIdx.x, w = tid >> 5, lane = tid & 31;
    const float* hrow = g_hid + (size_t)b * MH;
    for (int c = w; c < NC; c += 8) {
        float s = 0.f;
        for (int i = lane; i < MH; i += 32) s = fmaf(hrow[i], w2[(size_t)i * NC + c], s);
        #pragma unroll
        for (int o = 16; o; o >>= 1) s += __shfl_xor_sync(0xffffffffu, s, o);
        if (lane == 0) out[b * NC + c] = s + b2[c];
    }
}

// ---------------- launch ----------------
extern "C" void kernel_launch(void* const* d_in, const int* in_sizes, int n_in,
                              void* d_out, int out_size) {
    (void)in_sizes; (void)n_in; (void)out_size;
    const float* x    = (const float*)d_in[0];
    const float* chq  = (const float*)d_in[1];
    const float* clq  = (const float*)d_in[2];
    const float* chw  = (const float*)d_in[3];
    const float* chb  = (const float*)d_in[4];
    const float* chow = (const float*)d_in[5];
    const float* chob = (const float*)d_in[6];
    const float* tw   = (const float*)d_in[7];
    const float* tb   = (const float*)d_in[8];
    const float* tow  = (const float*)d_in[9];
    const float* tob  = (const float*)d_in[10];
    const float* qn_g = (const float*)d_in[11];
    const float* qn_b = (const float*)d_in[12];
    const float* cn_g = (const float*)d_in[13];
    const float* cn_b = (const float*)d_in[14];
    const float* pnc_g = (const float*)d_in[15];
    const float* pnc_b = (const float*)d_in[16];
    const float* pnp_g = (const float*)d_in[17];
    const float* pnp_b = (const float*)d_in[18];
    const float* pon_g = (const float*)d_in[19];
    const float* pon_b = (const float*)d_in[20];
    const float* w1 = (const float*)d_in[21];
    const float* b1 = (const float*)d_in[22];
    const float* w2 = (const float*)d_in[23];
    const float* b2 = (const float*)d_in[24];
    float* out = (float*)d_out;

    float *p_qln, *p_z, *p_p2, *p_hid;
    bf16 *mxh, *mxl, *plh, *pll, *m2h, *m2l, *p2h, *p2l, *lnh, *lnl;
    bf16 *wvh, *wvl, *cwh, *cwl, *w2h, *w2l, *toh, *tol, *w1h, *w1l;
    cudaGetSymbolAddress((void**)&p_qln, g_qln);
    cudaGetSymbolAddress((void**)&p_z, g_z);
    cudaGetSymbolAddress((void**)&p_p2, g_p2);
    cudaGetSymbolAddress((void**)&p_hid, g_hid);
    cudaGetSymbolAddress((void**)&mxh, g_mx_h);     cudaGetSymbolAddress((void**)&mxl, g_mx_l);
    cudaGetSymbolAddress((void**)&plh, g_pooled_h); cudaGetSymbolAddress((void**)&pll, g_pooled_l);
    cudaGetSymbolAddress((void**)&m2h, g_mx2_h);    cudaGetSymbolAddress((void**)&m2l, g_mx2_l);
    cudaGetSymbolAddress((void**)&p2h, g_pooled2_h);cudaGetSymbolAddress((void**)&p2l, g_pooled2_l);
    cudaGetSymbolAddress((void**)&lnh, g_p2ln_h);   cudaGetSymbolAddress((void**)&lnl, g_p2ln_l);
    cudaGetSymbolAddress((void**)&wvh, g_wvT_h);    cudaGetSymbolAddress((void**)&wvl, g_wvT_l);
    cudaGetSymbolAddress((void**)&cwh, g_chowT_h);  cudaGetSymbolAddress((void**)&cwl, g_chowT_l);
    cudaGetSymbolAddress((void**)&w2h, g_wv2T_h);   cudaGetSymbolAddress((void**)&w2l, g_wv2T_l);
    cudaGetSymbolAddress((void**)&toh, g_towT_h);   cudaGetSymbolAddress((void**)&tol, g_towT_l);
    cudaGetSymbolAddress((void**)&w1h, g_w1T_h);    cudaGetSymbolAddress((void**)&w1l, g_w1T_l);

    cudaFuncSetAttribute(k_main, cudaFuncAttributeMaxDynamicSharedMemorySize, SMEM_MAIN);
    cudaFuncSetAttribute(k_mma, cudaFuncAttributeMaxDynamicSharedMemorySize, 3 * STG_B);
    const int MMS = 3 * STG_B;

    // weight prep
    k_trsplit<<<dim3(32, 32), 256>>>(chw, C3F, 2 * F_, wvh, wvl);
    k_trsplit<<<dim3(32, 32), 256>>>(chow, F_, 0, cwh, cwl);
    k_trsplit<<<dim3(32, 32), 256>>>(tw, C3F, 2 * F_, w2h, w2l);
    k_trsplit<<<dim3(32, 32), 256>>>(tow, F_, 0, toh, tol);
    k_trsplit<<<dim3(32, 128), 256>>>(w1, MH, 0, w1h, w1l);

    k_ln_row<<<1, 256>>>(chq, qn_g, qn_b, p_qln);
    k_ln_row<<<1, 256>>>(clq, pnc_g, pnc_b, p_qln + F_);
    k_qh<<<dim3(8, 2), 128>>>(chw, chb, tw, tb);
    k_fold<<<dim3(1024, 2), 128>>>(chw, chb, tw, tb);
    k_main<<<dim3(P_, B_), 256, SMEM_MAIN>>>(x);
    // pooled = mixed_h @ Wv_h + bv  -> hi/lo planes (batched over heads)
    k_mma<<<dim3(1, T_ / 128, H_), 256, MMS>>>(mxh, mxl, (long long)T_ * F_,
        wvh, wvl, (long long)64 * F_, chb + 2 * F_, 64,
        nullptr, plh, pll, F_, 64, 2);
    // z = pooled @ chow + chob (f32)
    k_mma<<<dim3(F_ / 64, T_ / 128, 1), 256, MMS>>>(plh, pll, 0,
        cwh, cwl, 0, chob, 0, p_z, nullptr, nullptr, F_, 0, 0);
    k_lnln<<<T_, 256>>>(cn_g, cn_b, pnp_g, pnp_b);
    k_sc2mix<<<B_, 256>>>();
    // pooled2 = mixed2_h @ Wv2_h + bv2 -> hi/lo planes
    k_mma<<<dim3(1, 1, H_), 256, MMS>>>(m2h, m2l, (long long)B_ * F_,
        w2h, w2l, (long long)64 * F_, tb + 2 * F_, 64,
        nullptr, p2h, p2l, F_, 64, 2);
    // p2 = pooled2 @ tow + tob (f32)
    k_mma<<<dim3(F_ / 64, 1, 1), 256, MMS>>>(p2h, p2l, 0,
        toh, tol, 0, tob, 0, p_p2, nullptr, nullptr, F_, 0, 0);
    k_ln_split<<<B_, 256>>>(p_p2, pon_g, pon_b, lnh, lnl);
    // hid = gelu(p2ln @ w1 + b1)
    k_mma<<<dim3(MH / 64, 1, 1), 256, MMS>>>(lnh, lnl, 0,
        w1h, w1l, 0, b1, 0, p_hid, nullptr, nullptr, MH, 0, 1);
    k_logits<<<B_, 256>>>(w2, b2, out);
}

// round 14
// speedup vs baseline: 2.0568x; 1.1051x over previous
#include <cuda_runtime.h>
#include <cuda_bf16.h>
#include <math.h>
#include <stdint.h>

#define F_  1024
#define H_  16
#define D_  18
#define P_  64
#define B_  128
#define T_  8192
#define C3F 3072
#define NC  23
#define MH  4096

typedef __nv_bfloat16 bf16;
typedef unsigned long long u64;

__device__ float g_qln[2][F_];
__device__ float g_qh[2][F_];
__device__ __align__(16) float g_wkeff[2][H_ * F_];
__device__ float g_bkeff[2][H_];
__device__ float g_z[(size_t)T_ * F_];
__device__ float g_kv[(size_t)T_ * F_];
__device__ float g_p2[B_ * F_];
__device__ float g_hid[B_ * MH];
__device__ __align__(16) bf16 g_mx_h[(size_t)H_ * T_ * F_], g_mx_l[(size_t)H_ * T_ * F_];
__device__ __align__(16) bf16 g_pooled_h[(size_t)T_ * F_], g_pooled_l[(size_t)T_ * F_];
__device__ __align__(16) bf16 g_mx2_h[H_ * B_ * F_], g_mx2_l[H_ * B_ * F_];
__device__ __align__(16) bf16 g_pooled2_h[B_ * F_], g_pooled2_l[B_ * F_];
__device__ __align__(16) bf16 g_p2ln_h[B_ * F_], g_p2ln_l[B_ * F_];
__device__ __align__(16) bf16 g_wvT_h[F_ * F_],  g_wvT_l[F_ * F_];
__device__ __align__(16) bf16 g_chowT_h[F_ * F_], g_chowT_l[F_ * F_];
__device__ __align__(16) bf16 g_wv2T_h[F_ * F_], g_wv2T_l[F_ * F_];
__device__ __align__(16) bf16 g_towT_h[F_ * F_], g_towT_l[F_ * F_];
__device__ __align__(16) bf16 g_w1T_h[MH * F_],  g_w1T_l[MH * F_];

__device__ __forceinline__ uint32_t smem_u32(const void* p) {
    uint32_t a;
    asm("{ .reg .u64 t; cvta.to.shared.u64 t, %1; cvt.u32.u64 %0, t; }" : "=r"(a) : "l"(p));
    return a;
}
__device__ __forceinline__ void ldsm4(uint32_t& r0, uint32_t& r1, uint32_t& r2, uint32_t& r3, uint32_t a) {
    asm volatile("ldmatrix.sync.aligned.m8n8.x4.shared.b16 {%0,%1,%2,%3}, [%4];"
        : "=r"(r0), "=r"(r1), "=r"(r2), "=r"(r3) : "r"(a));
}
__device__ __forceinline__ void mma_bf16(float* c, const uint32_t* a, uint32_t b0, uint32_t b1) {
    asm volatile("mma.sync.aligned.m16n8k16.row.col.f32.bf16.bf16.f32 "
        "{%0,%1,%2,%3},{%4,%5,%6,%7},{%8,%9},{%0,%1,%2,%3};"
        : "+f"(c[0]), "+f"(c[1]), "+f"(c[2]), "+f"(c[3])
        : "r"(a[0]), "r"(a[1]), "r"(a[2]), "r"(a[3]), "r"(b0), "r"(b1));
}
#define CP16(dst, src) asm volatile("cp.async.cg.shared.global [%0], [%1], 16;" :: "r"(dst), "l"(src))
#define CPCOMMIT()     asm volatile("cp.async.commit_group;" ::: "memory")
#define CPWAIT(n)      asm volatile("cp.async.wait_group %0;" :: "n"(n) : "memory")
#define FMA2(d, a, b)  asm("fma.rn.f32x2 %0, %1, %2, %0;" : "+l"(d) : "l"(a), "l"(b))

__device__ __forceinline__ void sp2(float v0, float v1, uint32_t& h, uint32_t& l) {
    bf16 h0 = __float2bfloat16(v0), h1 = __float2bfloat16(v1);
    bf16 l0 = __float2bfloat16(v0 - __bfloat162float(h0));
    bf16 l1 = __float2bfloat16(v1 - __bfloat162float(h1));
    h = ((uint32_t)__bfloat16_as_ushort(h1) << 16) | __bfloat16_as_ushort(h0);
    l = ((uint32_t)__bfloat16_as_ushort(l1) << 16) | __bfloat16_as_ushort(l0);
}
__device__ __forceinline__ float block_sum_256(float v, float* red) {
    #pragma unroll
    for (int o = 16; o; o >>= 1) v += __shfl_xor_sync(0xffffffffu, v, o);
    int w = threadIdx.x >> 5;
    if ((threadIdx.x & 31) == 0) red[w] = v;
    __syncthreads();
    float s = red[0];
    #pragma unroll
    for (int i = 1; i < 8; i++) s += red[i];
    __syncthreads();
    return s;
}

// ---------------- weight transpose + split ----------------
__global__ __launch_bounds__(256) void k_trsplit(const float* __restrict__ src, int lds, int ofs,
                                                 bf16* __restrict__ dh, bf16* __restrict__ dl) {
    __shared__ float t[32][33];
    int k0 = blockIdx.x * 32, n0 = blockIdx.y * 32;
    int tx = threadIdx.x & 31, ty = threadIdx.x >> 5;
    #pragma unroll
    for (int j = 0; j < 4; j++)
        t[ty + j * 8][tx] = src[(size_t)(k0 + ty + j * 8) * lds + ofs + n0 + tx];
    __syncthreads();
    #pragma unroll
    for (int j = 0; j < 4; j++) {
        int r = ty + j * 8;
        float v = t[tx][r];
        bf16 h = __float2bfloat16(v);
        bf16 l = __float2bfloat16(v - __bfloat162float(h));
        size_t o = (size_t)(n0 + r) * F_ + k0 + tx;
        dh[o] = h; dl[o] = l;
    }
}

// ---------------- cp.async 3-stage split-bf16 GEMM (proven R9 version) ----------------
#define STG_B 18432
__global__ __launch_bounds__(256) void k_mma(
    const bf16* __restrict__ Ah, const bf16* __restrict__ Al, long long sA,
    const bf16* __restrict__ Bh, const bf16* __restrict__ Bl, long long sB,
    const float* __restrict__ bias, long long sBias,
    float* __restrict__ Cf, bf16* __restrict__ Ch, bf16* __restrict__ Cl,
    int ldc, long long sC, int mode)
{
    extern __shared__ bf16 s[];
    int z = blockIdx.z;
    Ah += (size_t)z * sA; Al += (size_t)z * sA;
    Bh += (size_t)z * sB; Bl += (size_t)z * sB;
    const float* bz = bias + (size_t)z * sBias;
    const int tM = blockIdx.y * 128, tN = blockIdx.x * 64;
    const int t = threadIdx.x, wid = t >> 5, lane = t & 31;
    const int m_idx = wid >> 1, n_idx = wid & 1;
    uint32_t sbase = smem_u32(s);

    const int ar = t >> 1, aseg = t & 1;
    const bf16* agh = Ah + (size_t)(tM + ar) * F_ + aseg * 8;
    const bf16* agl = Al + (size_t)(tM + ar) * F_ + aseg * 8;
    const uint32_t adst = ar * 48 + aseg * 16;
    const int br = (t & 127) >> 1, bseg = t & 1;
    const bf16* bgp = ((t < 128) ? Bh : Bl) + (size_t)(tN + br) * F_ + bseg * 8;
    const uint32_t bdst = 12288 + ((t >= 128) ? 3072u : 0u) + br * 48 + bseg * 16;

    uint32_t oA[2], oB[2];
    #pragma unroll
    for (int ti = 0; ti < 2; ti++) {
        int r = m_idx * 32 + ti * 16 + (lane & 15);
        oA[ti] = r * 48 + (lane >> 4) * 16;
    }
    #pragma unroll
    for (int gi = 0; gi < 2; gi++) {
        int mtx = lane >> 3;
        int nr = n_idx * 32 + gi * 16 + (mtx >> 1) * 8 + (lane & 7);
        oB[gi] = 12288 + nr * 48 + (mtx & 1) * 16;
    }

    float acc[2][4][4];
    #pragma unroll
    for (int i = 0; i < 2; i++)
        #pragma unroll
        for (int j = 0; j < 4; j++)
            #pragma unroll
            for (int k = 0; k < 4; k++) acc[i][j][k] = 0.f;

    #pragma unroll
    for (int sp = 0; sp < 2; sp++) {
        uint32_t sb = sbase + sp * STG_B;
        CP16(sb + adst, agh + sp * 16);
        CP16(sb + 6144 + adst, agl + sp * 16);
        CP16(sb + bdst, bgp + sp * 16);
        CPCOMMIT();
    }

    for (int c = 0; c < 64; c++) {
        if (c < 62) {
            int nc = c + 2;
            uint32_t sb = sbase + (nc % 3) * STG_B;
            CP16(sb + adst, agh + nc * 16);
            CP16(sb + 6144 + adst, agl + nc * 16);
            CP16(sb + bdst, bgp + nc * 16);
            CPCOMMIT();
            CPWAIT(2);
        } else if (c == 62) CPWAIT(1);
        else CPWAIT(0);
        __syncthreads();

        uint32_t sb = sbase + (c % 3) * STG_B;
        uint32_t Ahf[2][4], Alf[2][4], Bhf[2][4], Blf[2][4];
        #pragma unroll
        for (int ti = 0; ti < 2; ti++) {
            ldsm4(Ahf[ti][0], Ahf[ti][1], Ahf[ti][2], Ahf[ti][3], sb + oA[ti]);
            ldsm4(Alf[ti][0], Alf[ti][1], Alf[ti][2], Alf[ti][3], sb + 6144 + oA[ti]);
        }
        #pragma unroll
        for (int gi = 0; gi < 2; gi++) {
            ldsm4(Bhf[gi][0], Bhf[gi][1], Bhf[gi][2], Bhf[gi][3], sb + oB[gi]);
            ldsm4(Blf[gi][0], Blf[gi][1], Blf[gi][2], Blf[gi][3], sb + 3072 + oB[gi]);
        }
        #pragma unroll
        for (int ti = 0; ti < 2; ti++)
            #pragma unroll
            for (int gi = 0; gi < 2; gi++)
                #pragma unroll
                for (int sub = 0; sub < 2; sub++) {
                    int tn = gi * 2 + sub;
                    mma_bf16(acc[ti][tn], Ahf[ti], Bhf[gi][2 * sub], Bhf[gi][2 * sub + 1]);
                    mma_bf16(acc[ti][tn], Ahf[ti], Blf[gi][2 * sub], Blf[gi][2 * sub + 1]);
                    mma_bf16(acc[ti][tn], Alf[ti], Bhf[gi][2 * sub], Bhf[gi][2 * sub + 1]);
                }
        __syncthreads();
    }

    const int g = lane >> 2, tg = lane & 3;
    #pragma unroll
    for (int ti = 0; ti < 2; ti++) {
        int r0 = tM + m_idx * 32 + ti * 16 + g;
        #pragma unroll
        for (int tn = 0; tn < 4; tn++) {
            int col = tN + n_idx * 32 + tn * 8 + tg * 2;
            float b0 = bz[col], b1 = bz[col + 1];
            float v0 = acc[ti][tn][0] + b0, v1 = acc[ti][tn][1] + b1;
            float v2 = acc[ti][tn][2] + b0, v3 = acc[ti][tn][3] + b1;
            if (mode == 1) {
                v0 = 0.5f * v0 * (1.f + erff(v0 * 0.70710678118654752f));
                v1 = 0.5f * v1 * (1.f + erff(v1 * 0.70710678118654752f));
                v2 = 0.5f * v2 * (1.f + erff(v2 * 0.70710678118654752f));
                v3 = 0.5f * v3 * (1.f + erff(v3 * 0.70710678118654752f));
            }
            if (mode == 2) {
                uint32_t h, l;
                sp2(v0, v1, h, l);
                *(uint32_t*)(Ch + (size_t)z * sC + (size_t)r0 * ldc + col) = h;
                *(uint32_t*)(Cl + (size_t)z * sC + (size_t)r0 * ldc + col) = l;
                sp2(v2, v3, h, l);
                *(uint32_t*)(Ch + (size_t)z * sC + (size_t)(r0 + 8) * ldc + col) = h;
                *(uint32_t*)(Cl + (size_t)z * sC + (size_t)(r0 + 8) * ldc + col) = l;
            } else {
                float* Cz = Cf + (size_t)z * sC;
                *(float2*)(Cz + (size_t)r0 * ldc + col)       = make_float2(v0, v1);
                *(float2*)(Cz + (size_t)(r0 + 8) * ldc + col) = make_float2(v2, v3);
            }
        }
    }
}

// ---------------- LayerNorms ----------------
__global__ __launch_bounds__(256) void k_ln_row(const float* __restrict__ src,
                                                const float* __restrict__ g,
                                                const float* __restrict__ b,
                                                float* __restrict__ dst) {
    __shared__ float red[8];
    size_t row = blockIdx.x;
    int tid = threadIdx.x;
    float4 v = ((const float4*)src)[row * 256 + tid];
    float m = block_sum_256(v.x + v.y + v.z + v.w, red) * (1.f / 1024.f);
    float dx = v.x - m, dy = v.y - m, dz = v.z - m, dw = v.w - m;
    float var = block_sum_256(dx*dx + dy*dy + dz*dz + dw*dw, red) * (1.f / 1024.f);
    float rs = rsqrtf(var + 1e-5f);
    float4 gv = ((const float4*)g)[tid], bv = ((const float4*)b)[tid];
    float4 o;
    o.x = dx * rs * gv.x + bv.x; o.y = dy * rs * gv.y + bv.y;
    o.z = dz * rs * gv.z + bv.z; o.w = dw * rs * gv.w + bv.w;
    ((float4*)dst)[row * 256 + tid] = o;
}

__global__ __launch_bounds__(256) void k_ln_split(const float* __restrict__ src,
                                                  const float* __restrict__ g,
                                                  const float* __restrict__ b,
                                                  bf16* __restrict__ dh, bf16* __restrict__ dl) {
    __shared__ float red[8];
    size_t row = blockIdx.x;
    int tid = threadIdx.x;
    float4 v = ((const float4*)src)[row * 256 + tid];
    float m = block_sum_256(v.x + v.y + v.z + v.w, red) * (1.f / 1024.f);
    float dx = v.x - m, dy = v.y - m, dz = v.z - m, dw = v.w - m;
    float var = block_sum_256(dx*dx + dy*dy + dz*dz + dw*dw, red) * (1.f / 1024.f);
    float rs = rsqrtf(var + 1e-5f);
    float4 gv = ((const float4*)g)[tid], bv = ((const float4*)b)[tid];
    float o0 = dx * rs * gv.x + bv.x, o1 = dy * rs * gv.y + bv.y;
    float o2 = dz * rs * gv.z + bv.z, o3 = dw * rs * gv.w + bv.w;
    uint2 uh, ul;
    sp2(o0, o1, uh.x, ul.x);
    sp2(o2, o3, uh.y, ul.y);
    ((uint2*)dh)[row * 256 + tid] = uh;
    ((uint2*)dl)[row * 256 + tid] = ul;
}

__global__ __launch_bounds__(128) void k_qh(const float* __restrict__ chw, const float* __restrict__ chb,
                                            const float* __restrict__ tw, const float* __restrict__ tb) {
    int side = blockIdx.y;
    const float* W  = side ? tw : chw;
    const float* bb = side ? tb : chb;
    const float* q  = g_qln[side];
    __shared__ float qs[F_];
    int tid = threadIdx.x;
    for (int i = tid; i < F_; i += 128) qs[i] = q[i];
    __syncthreads();
    int j = blockIdx.x * 128 + tid;
    float a0 = 0.f, a1 = 0.f, a2 = 0.f, a3 = 0.f;
    for (int f = 0; f < F_; f += 4) {
        a0 = fmaf(qs[f], W[(size_t)f * C3F + j], a0);
        a1 = fmaf(qs[f + 1], W[(size_t)(f + 1) * C3F + j], a1);
        a2 = fmaf(qs[f + 2], W[(size_t)(f + 2) * C3F + j], a2);
        a3 = fmaf(qs[f + 3], W[(size_t)(f + 3) * C3F + j], a3);
    }
    g_qh[side][j] = a0 + a1 + a2 + a3 + bb[j];
}

__global__ __launch_bounds__(128) void k_fold(const float* __restrict__ chw, const float* __restrict__ chb,
                                              const float* __restrict__ tw, const float* __restrict__ tb) {
    int side = blockIdx.y, f = blockIdx.x, tid = threadIdx.x;
    const float* W  = side ? tw : chw;
    const float* qh = g_qh[side];
    __shared__ float wrow[F_];
    for (int i = tid; i < F_; i += 128) wrow[i] = W[(size_t)f * C3F + F_ + i];
    __syncthreads();
    int h = tid >> 3, i8 = tid & 7;
    float s = 0.f;
    #pragma unroll
    for (int d = 0; d < 8; d++) s += wrow[h * 64 + i8 * 8 + d] * qh[h * 64 + i8 * 8 + d];
    s += __shfl_down_sync(0xffffffffu, s, 4, 8);
    s += __shfl_down_sync(0xffffffffu, s, 2, 8);
    s += __shfl_down_sync(0xffffffffu, s, 1, 8);
    if (i8 == 0) g_wkeff[side][h * F_ + f] = s;
    if (f == 0 && tid < H_) {
        const float* bb = side ? tb : chb;
        float bs = 0.f;
        for (int d = 0; d < 64; d++) bs += bb[F_ + tid * 64 + d] * qh[tid * 64 + d];
        g_bkeff[side][tid] = bs;
    }
}

// ---------------- fused stage-1 v3: FFMA2 + col-split score warps ----------------
#define SMEM_MAIN (D_ * F_ * 4 + 2 * 288 * 4 + 288 * 4 + 288 * 8)
__global__ __launch_bounds__(256) void k_main(const float* __restrict__ x) {
    extern __shared__ float sm[];
    float* xs   = sm;                          // [18][1024]
    float* part = xs + D_ * F_;                // [2][288]
    float* sc   = part + 2 * 288;              // [288]
    u64* attnP  = (u64*)(sc + 288);            // [k*16+h]

    int p = blockIdx.x, b = blockIdx.y, tid = threadIdx.x;
    int t = b * P_ + p;
    int w = tid >> 5, lane = tid & 31;
    int cg = w & 1, hg = w >> 1;

    ulonglong2 wk[4][4];
    #pragma unroll
    for (int hh = 0; hh < 4; hh++) {
        const ulonglong2* wr = (const ulonglong2*)(g_wkeff[0] + (hg * 4 + hh) * F_ + cg * 512);
        #pragma unroll
        for (int i = 0; i < 4; i++) wk[hh][i] = wr[lane + i * 32];
    }

    const float4* xg = (const float4*)x;
    #pragma unroll
    for (int k = 0; k < D_; k++)
        ((float4*)xs)[k * 256 + tid] = xg[((size_t)(b * D_ + k) * P_ + p) * 256 + tid];
    __syncthreads();

    for (int k = 0; k < D_; k++) {
        const ulonglong2* xr = (const ulonglong2*)(xs + k * F_ + cg * 512);
        ulonglong2 xv[4];
        #pragma unroll
        for (int i = 0; i < 4; i++) xv[i] = xr[lane + i * 32];
        #pragma unroll
        for (int hh = 0; hh < 4; hh++) {
            u64 s2 = 0;
            #pragma unroll
            for (int i = 0; i < 4; i++) {
                FMA2(s2, xv[i].x, wk[hh][i].x);
                FMA2(s2, xv[i].y, wk[hh][i].y);
            }
            float s = __uint_as_float((unsigned)s2) + __uint_as_float((unsigned)(s2 >> 32));
            #pragma unroll
            for (int o = 16; o; o >>= 1) s += __shfl_xor_sync(0xffffffffu, s, o);
            if (lane == 0) part[cg * 288 + (hg * 4 + hh) * D_ + k] = s;
        }
    }
    __syncthreads();

    for (int pair = tid; pair < 288; pair += 256)
        sc[pair] = (part[pair] + part[288 + pair] + g_bkeff[0][pair / D_]) * 0.125f;
    __syncthreads();

    if (tid < H_) {
        int h = tid;
        float mx = -1e30f;
        #pragma unroll
        for (int k = 0; k < D_; k++) mx = fmaxf(mx, sc[h * D_ + k]);
        float e[D_], ss = 0.f;
        #pragma unroll
        for (int k = 0; k < D_; k++) { e[k] = expf(sc[h * D_ + k] - mx); ss += e[k]; }
        float inv = 1.f / ss;
        #pragma unroll
        for (int k = 0; k < D_; k++) {
            unsigned u = __float_as_uint(e[k] * inv);
            attnP[k * H_ + h] = ((u64)u << 32) | u;
        }
    }
    __syncthreads();

    ulonglong2 acc2[H_];
    #pragma unroll
    for (int h = 0; h < H_; h++) { acc2[h].x = 0; acc2[h].y = 0; }
    #pragma unroll
    for (int k = 0; k < D_; k++) {
        ulonglong2 xv = ((const ulonglong2*)xs)[k * 256 + tid];
        const u64* ap = attnP + k * H_;
        #pragma unroll
        for (int h = 0; h < H_; h++) {
            u64 a = ap[h];
            FMA2(acc2[h].x, a, xv.x);
            FMA2(acc2[h].y, a, xv.y);
        }
    }
    #pragma unroll
    for (int h = 0; h < H_; h++) {
        float f0 = __uint_as_float((unsigned)acc2[h].x);
        float f1 = __uint_as_float((unsigned)(acc2[h].x >> 32));
        float f2 = __uint_as_float((unsigned)acc2[h].y);
        float f3 = __uint_as_float((unsigned)(acc2[h].y >> 32));
        uint2 uh, ul;
        sp2(f0, f1, uh.x, ul.x);
        sp2(f2, f3, uh.y, ul.y);
        size_t o = ((size_t)h * T_ + t) * 256 + tid;
        ((uint2*)g_mx_h)[o] = uh;
        ((uint2*)g_mx_l)[o] = ul;
    }
}

// ---------------- kv = ln(ln(z, cn), pnp) ----------------
__global__ __launch_bounds__(256) void k_lnln(const float* __restrict__ g1, const float* __restrict__ b1,
                                              const float* __restrict__ g2, const float* __restrict__ b2) {
    __shared__ float red[8];
    size_t row = blockIdx.x;
    int tid = threadIdx.x;
    float4 v = ((const float4*)g_z)[row * 256 + tid];
    float m = block_sum_256(v.x + v.y + v.z + v.w, red) * (1.f / 1024.f);
    float dx = v.x - m, dy = v.y - m, dz = v.z - m, dw = v.w - m;
    float var = block_sum_256(dx*dx + dy*dy + dz*dz + dw*dw, red) * (1.f / 1024.f);
    float rs = rsqrtf(var + 1e-5f);
    float4 g1v = ((const float4*)g1)[tid], b1v = ((const float4*)b1)[tid];
    float yx = dx * rs * g1v.x + b1v.x, yy = dy * rs * g1v.y + b1v.y;
    float yz = dz * rs * g1v.z + b1v.z, yw = dw * rs * g1v.w + b1v.w;
    float m2 = block_sum_256(yx + yy + yz + yw, red) * (1.f / 1024.f);
    float ex = yx - m2, ey = yy - m2, ez = yz - m2, ew = yw - m2;
    float var2 = block_sum_256(ex*ex + ey*ey + ez*ez + ew*ew, red) * (1.f / 1024.f);
    float rs2 = rsqrtf(var2 + 1e-5f);
    float4 g2v = ((const float4*)g2)[tid], b2v = ((const float4*)b2)[tid];
    float4 o;
    o.x = ex * rs2 * g2v.x + b2v.x; o.y = ey * rs2 * g2v.y + b2v.y;
    o.z = ez * rs2 * g2v.z + b2v.z; o.w = ew * rs2 * g2v.w + b2v.w;
    ((float4*)g_kv)[row * 256 + tid] = o;
}

// ---------------- stage-2 fused ----------------
__global__ __launch_bounds__(256) void k_sc2mix() {
    __shared__ float sc[H_ * P_];
    int b = blockIdx.x, tid = threadIdx.x, w = tid >> 5, lane = tid & 31;
    for (int j = 0; j < 128; j++) {
        int pair = w + 8 * j;
        int h = pair >> 6, p = pair & 63;
        const float4* kr = (const float4*)(g_kv + (size_t)(b * P_ + p) * F_);
        const float4* wr = (const float4*)(g_wkeff[1] + h * F_);
        float s = 0.f;
        #pragma unroll
        for (int i = 0; i < 8; i++) {
            float4 a = kr[lane + 32 * i], bv = wr[lane + 32 * i];
            s = fmaf(a.x, bv.x, s); s = fmaf(a.y, bv.y, s);
            s = fmaf(a.z, bv.z, s); s = fmaf(a.w, bv.w, s);
        }
        #pragma unroll
        for (int o = 16; o; o >>= 1) s += __shfl_xor_sync(0xffffffffu, s, o);
        if (lane == 0) sc[h * P_ + p] = (s + g_bkeff[1][h]) * 0.125f;
    }
    __syncthreads();
    if (tid < H_) {
        int h = tid;
        float mx = -1e30f;
        for (int p = 0; p < P_; p++) mx = fmaxf(mx, sc[h * P_ + p]);
        float ss = 0.f;
        for (int p = 0; p < P_; p++) { float e = expf(sc[h * P_ + p] - mx); sc[h * P_ + p] = e; ss += e; }
        float inv = 1.f / ss;
        for (int p = 0; p < P_; p++) sc[h * P_ + p] *= inv;
    }
    __syncthreads();
    float4 acc[H_];
    #pragma unroll
    for (int h = 0; h < H_; h++) acc[h] = make_float4(0.f, 0.f, 0.f, 0.f);
    for (int p = 0; p < P_; p++) {
        float4 xv = ((const float4*)g_kv)[(size_t)(b * P_ + p) * 256 + tid];
        #pragma unroll
        for (int h = 0; h < H_; h++) {
            float a = sc[h * P_ + p];
            acc[h].x = fmaf(a, xv.x, acc[h].x); acc[h].y = fmaf(a, xv.y, acc[h].y);
            acc[h].z = fmaf(a, xv.z, acc[h].z); acc[h].w = fmaf(a, xv.w, acc[h].w);
        }
    }
    #pragma unroll
    for (int h = 0; h < H_; h++) {
        uint2 uh, ul;
        sp2(acc[h].x, acc[h].y, uh.x, ul.x);
        sp2(acc[h].z, acc[h].w, uh.y, ul.y);
        size_t o = (size_t)(h * B_ + b) * 256 + tid;
        ((uint2*)g_mx2_h)[o] = uh;
        ((uint2*)g_mx2_l)[o] = ul;
    }
}

__global__ __launch_bounds__(256) void k_logits(const float* __restrict__ w2,
                                                const float* __restrict__ b2,
                                                float* __restrict__ out) {
    int b = blockIdx.x, tid = threadIdx.x, w = tid >> 5, lane = tid & 31;
    const float* hrow = g_hid + (size_t)b * MH;
    for (int c = w; c < NC; c += 8) {
        float s = 0.f;
        for (int i = lane; i < MH; i += 32) s = fmaf(hrow[i], w2[(size_t)i * NC + c], s);
        #pragma unroll
        for (int o = 16; o; o >>= 1) s += __shfl_xor_sync(0xffffffffu, s, o);
        if (lane == 0) out[b * NC + c] = s + b2[c];
    }
}

// ---------------- launch ----------------
extern "C" void kernel_launch(void* const* d_in, const int* in_sizes, int n_in,
                              void* d_out, int out_size) {
    (void)in_sizes; (void)n_in; (void)out_size;
    const float* x    = (const float*)d_in[0];
    const float* chq  = (const float*)d_in[1];
    const float* clq  = (const float*)d_in[2];
    const float* chw  = (const float*)d_in[3];
    const float* chb  = (const float*)d_in[4];
    const float* chow = (const float*)d_in[5];
    const float* chob = (const float*)d_in[6];
    const float* tw   = (const float*)d_in[7];
    const float* tb   = (const float*)d_in[8];
    const float* tow  = (const float*)d_in[9];
    const float* tob  = (const float*)d_in[10];
    const float* qn_g = (const float*)d_in[11];
    const float* qn_b = (const float*)d_in[12];
    const float* cn_g = (const float*)d_in[13];
    const float* cn_b = (const float*)d_in[14];
    const float* pnc_g = (const float*)d_in[15];
    const float* pnc_b = (const float*)d_in[16];
    const float* pnp_g = (const float*)d_in[17];
    const float* pnp_b = (const float*)d_in[18];
    const float* pon_g = (const float*)d_in[19];
    const float* pon_b = (const float*)d_in[20];
    const float* w1 = (const float*)d_in[21];
    const float* b1 = (const float*)d_in[22];
    const float* w2 = (const float*)d_in[23];
    const float* b2 = (const float*)d_in[24];
    float* out = (float*)d_out;

    float *p_qln, *p_z, *p_p2, *p_hid;
    bf16 *mxh, *mxl, *plh, *pll, *m2h, *m2l, *p2h, *p2l, *lnh, *lnl;
    bf16 *wvh, *wvl, *cwh, *cwl, *w2h, *w2l, *toh, *tol, *w1h, *w1l;
    cudaGetSymbolAddress((void**)&p_qln, g_qln);
    cudaGetSymbolAddress((void**)&p_z, g_z);
    cudaGetSymbolAddress((void**)&p_p2, g_p2);
    cudaGetSymbolAddress((void**)&p_hid, g_hid);
    cudaGetSymbolAddress((void**)&mxh, g_mx_h);     cudaGetSymbolAddress((void**)&mxl, g_mx_l);
    cudaGetSymbolAddress((void**)&plh, g_pooled_h); cudaGetSymbolAddress((void**)&pll, g_pooled_l);
    cudaGetSymbolAddress((void**)&m2h, g_mx2_h);    cudaGetSymbolAddress((void**)&m2l, g_mx2_l);
    cudaGetSymbolAddress((void**)&p2h, g_pooled2_h);cudaGetSymbolAddress((void**)&p2l, g_pooled2_l);
    cudaGetSymbolAddress((void**)&lnh, g_p2ln_h);   cudaGetSymbolAddress((void**)&lnl, g_p2ln_l);
    cudaGetSymbolAddress((void**)&wvh, g_wvT_h);    cudaGetSymbolAddress((void**)&wvl, g_wvT_l);
    cudaGetSymbolAddress((void**)&cwh, g_chowT_h);  cudaGetSymbolAddress((void**)&cwl, g_chowT_l);
    cudaGetSymbolAddress((void**)&w2h, g_wv2T_h);   cudaGetSymbolAddress((void**)&w2l, g_wv2T_l);
    cudaGetSymbolAddress((void**)&toh, g_towT_h);   cudaGetSymbolAddress((void**)&tol, g_towT_l);
    cudaGetSymbolAddress((void**)&w1h, g_w1T_h);    cudaGetSymbolAddress((void**)&w1l, g_w1T_l);

    cudaFuncSetAttribute(k_main, cudaFuncAttributeMaxDynamicSharedMemorySize, SMEM_MAIN);
    cudaFuncSetAttribute(k_mma, cudaFuncAttributeMaxDynamicSharedMemorySize, 3 * STG_B);
    const int MMS = 3 * STG_B;

    k_trsplit<<<dim3(32, 32), 256>>>(chw, C3F, 2 * F_, wvh, wvl);
    k_trsplit<<<dim3(32, 32), 256>>>(chow, F_, 0, cwh, cwl);
    k_trsplit<<<dim3(32, 32), 256>>>(tw, C3F, 2 * F_, w2h, w2l);
    k_trsplit<<<dim3(32, 32), 256>>>(tow, F_, 0, toh, tol);
    k_trsplit<<<dim3(32, 128), 256>>>(w1, MH, 0, w1h, w1l);

    k_ln_row<<<1, 256>>>(chq, qn_g, qn_b, p_qln);
    k_ln_row<<<1, 256>>>(clq, pnc_g, pnc_b, p_qln + F_);
    k_qh<<<dim3(8, 2), 128>>>(chw, chb, tw, tb);
    k_fold<<<dim3(1024, 2), 128>>>(chw, chb, tw, tb);
    k_main<<<dim3(P_, B_), 256, SMEM_MAIN>>>(x);
    k_mma<<<dim3(1, T_ / 128, H_), 256, MMS>>>(mxh, mxl, (long long)T_ * F_,
        wvh, wvl, (long long)64 * F_, chb + 2 * F_, 64,
        nullptr, plh, pll, F_, 64, 2);
    k_mma<<<dim3(F_ / 64, T_ / 128, 1), 256, MMS>>>(plh, pll, 0,
        cwh, cwl, 0, chob, 0, p_z, nullptr, nullptr, F_, 0, 0);
    k_lnln<<<T_, 256>>>(cn_g, cn_b, pnp_g, pnp_b);
    k_sc2mix<<<B_, 256>>>();
    k_mma<<<dim3(1, 1, H_), 256, MMS>>>(m2h, m2l, (long long)B_ * F_,
        w2h, w2l, (long long)64 * F_, tb + 2 * F_, 64,
        nullptr, p2h, p2l, F_, 64, 2);
    k_mma<<<dim3(F_ / 64, 1, 1), 256, MMS>>>(p2h, p2l, 0,
        toh, tol, 0, tob, 0, p_p2, nullptr, nullptr, F_, 0, 0);
    k_ln_split<<<B_, 256>>>(p_p2, pon_g, pon_b, lnh, lnl);
    k_mma<<<dim3(MH / 64, 1, 1), 256, MMS>>>(lnh, lnl, 0,
        w1h, w1l, 0, b1, 0, p_hid, nullptr, nullptr, MH, 0, 1);
    k_logits<<<B_, 256>>>(w2, b2, out);
}

// round 15
// speedup vs baseline: 2.0643x; 1.0037x over previous
#include <cuda_runtime.h>
#include <cuda_bf16.h>
#include <math.h>
#include <stdint.h>

#define F_  1024
#define H_  16
#define D_  18
#define P_  64
#define B_  128
#define T_  8192
#define C3F 3072
#define NC  23
#define MH  4096

typedef __nv_bfloat16 bf16;
typedef unsigned long long u64;

__device__ float g_qln[2][F_];
__device__ float g_qh[2][F_];
__device__ __align__(16) float g_wkeff[2][H_ * F_];
__device__ float g_bkeff[2][H_];
__device__ float g_z[(size_t)T_ * F_];
__device__ float g_kv[(size_t)T_ * F_];
__device__ float g_p2[B_ * F_];
__device__ float g_hid[B_ * MH];
__device__ __align__(16) bf16 g_mx_h[(size_t)H_ * T_ * F_], g_mx_l[(size_t)H_ * T_ * F_];
__device__ __align__(16) bf16 g_pooled_h[(size_t)T_ * F_], g_pooled_l[(size_t)T_ * F_];
__device__ __align__(16) bf16 g_mx2_h[H_ * B_ * F_], g_mx2_l[H_ * B_ * F_];
__device__ __align__(16) bf16 g_pooled2_h[B_ * F_], g_pooled2_l[B_ * F_];
__device__ __align__(16) bf16 g_p2ln_h[B_ * F_], g_p2ln_l[B_ * F_];
__device__ __align__(16) bf16 g_wvT_h[F_ * F_],  g_wvT_l[F_ * F_];
__device__ __align__(16) bf16 g_chowT_h[F_ * F_], g_chowT_l[F_ * F_];
__device__ __align__(16) bf16 g_wv2T_h[F_ * F_], g_wv2T_l[F_ * F_];
__device__ __align__(16) bf16 g_towT_h[F_ * F_], g_towT_l[F_ * F_];
__device__ __align__(16) bf16 g_w1T_h[MH * F_],  g_w1T_l[MH * F_];

__device__ __forceinline__ uint32_t smem_u32(const void* p) {
    uint32_t a;
    asm("{ .reg .u64 t; cvta.to.shared.u64 t, %1; cvt.u32.u64 %0, t; }" : "=r"(a) : "l"(p));
    return a;
}
__device__ __forceinline__ void ldsm4(uint32_t& r0, uint32_t& r1, uint32_t& r2, uint32_t& r3, uint32_t a) {
    asm volatile("ldmatrix.sync.aligned.m8n8.x4.shared.b16 {%0,%1,%2,%3}, [%4];"
        : "=r"(r0), "=r"(r1), "=r"(r2), "=r"(r3) : "r"(a));
}
__device__ __forceinline__ void mma_bf16(float* c, const uint32_t* a, uint32_t b0, uint32_t b1) {
    asm volatile("mma.sync.aligned.m16n8k16.row.col.f32.bf16.bf16.f32 "
        "{%0,%1,%2,%3},{%4,%5,%6,%7},{%8,%9},{%0,%1,%2,%3};"
        : "+f"(c[0]), "+f"(c[1]), "+f"(c[2]), "+f"(c[3])
        : "r"(a[0]), "r"(a[1]), "r"(a[2]), "r"(a[3]), "r"(b0), "r"(b1));
}
#define CP16(dst, src) asm volatile("cp.async.cg.shared.global [%0], [%1], 16;" :: "r"(dst), "l"(src))
#define CPCOMMIT()     asm volatile("cp.async.commit_group;" ::: "memory")
#define CPWAIT(n)      asm volatile("cp.async.wait_group %0;" :: "n"(n) : "memory")
#define FMA2(d, a, b)  asm("fma.rn.f32x2 %0, %1, %2, %0;" : "+l"(d) : "l"(a), "l"(b))

__device__ __forceinline__ void sp2(float v0, float v1, uint32_t& h, uint32_t& l) {
    bf16 h0 = __float2bfloat16(v0), h1 = __float2bfloat16(v1);
    bf16 l0 = __float2bfloat16(v0 - __bfloat162float(h0));
    bf16 l1 = __float2bfloat16(v1 - __bfloat162float(h1));
    h = ((uint32_t)__bfloat16_as_ushort(h1) << 16) | __bfloat16_as_ushort(h0);
    l = ((uint32_t)__bfloat16_as_ushort(l1) << 16) | __bfloat16_as_ushort(l0);
}
__device__ __forceinline__ float block_sum_256(float v, float* red) {
    #pragma unroll
    for (int o = 16; o; o >>= 1) v += __shfl_xor_sync(0xffffffffu, v, o);
    int w = threadIdx.x >> 5;
    if ((threadIdx.x & 31) == 0) red[w] = v;
    __syncthreads();
    float s = red[0];
    #pragma unroll
    for (int i = 1; i < 8; i++) s += red[i];
    __syncthreads();
    return s;
}

// ---------------- weight transpose + split ----------------
__global__ __launch_bounds__(256) void k_trsplit(const float* __restrict__ src, int lds, int ofs,
                                                 bf16* __restrict__ dh, bf16* __restrict__ dl) {
    __shared__ float t[32][33];
    int k0 = blockIdx.x * 32, n0 = blockIdx.y * 32;
    int tx = threadIdx.x & 31, ty = threadIdx.x >> 5;
    #pragma unroll
    for (int j = 0; j < 4; j++)
        t[ty + j * 8][tx] = src[(size_t)(k0 + ty + j * 8) * lds + ofs + n0 + tx];
    __syncthreads();
    #pragma unroll
    for (int j = 0; j < 4; j++) {
        int r = ty + j * 8;
        float v = t[tx][r];
        bf16 h = __float2bfloat16(v);
        bf16 l = __float2bfloat16(v - __bfloat162float(h));
        size_t o = (size_t)(n0 + r) * F_ + k0 + tx;
        dh[o] = h; dl[o] = l;
    }
}

// ---------------- cp.async 3-stage split-bf16 GEMM (proven) ----------------
#define STG_B 18432
__global__ __launch_bounds__(256) void k_mma(
    const bf16* __restrict__ Ah, const bf16* __restrict__ Al, long long sA,
    const bf16* __restrict__ Bh, const bf16* __restrict__ Bl, long long sB,
    const float* __restrict__ bias, long long sBias,
    float* __restrict__ Cf, bf16* __restrict__ Ch, bf16* __restrict__ Cl,
    int ldc, long long sC, int mode)
{
    extern __shared__ bf16 s[];
    int z = blockIdx.z;
    Ah += (size_t)z * sA; Al += (size_t)z * sA;
    Bh += (size_t)z * sB; Bl += (size_t)z * sB;
    const float* bz = bias + (size_t)z * sBias;
    const int tM = blockIdx.y * 128, tN = blockIdx.x * 64;
    const int t = threadIdx.x, wid = t >> 5, lane = t & 31;
    const int m_idx = wid >> 1, n_idx = wid & 1;
    uint32_t sbase = smem_u32(s);

    const int ar = t >> 1, aseg = t & 1;
    const bf16* agh = Ah + (size_t)(tM + ar) * F_ + aseg * 8;
    const bf16* agl = Al + (size_t)(tM + ar) * F_ + aseg * 8;
    const uint32_t adst = ar * 48 + aseg * 16;
    const int br = (t & 127) >> 1, bseg = t & 1;
    const bf16* bgp = ((t < 128) ? Bh : Bl) + (size_t)(tN + br) * F_ + bseg * 8;
    const uint32_t bdst = 12288 + ((t >= 128) ? 3072u : 0u) + br * 48 + bseg * 16;

    uint32_t oA[2], oB[2];
    #pragma unroll
    for (int ti = 0; ti < 2; ti++) {
        int r = m_idx * 32 + ti * 16 + (lane & 15);
        oA[ti] = r * 48 + (lane >> 4) * 16;
    }
    #pragma unroll
    for (int gi = 0; gi < 2; gi++) {
        int mtx = lane >> 3;
        int nr = n_idx * 32 + gi * 16 + (mtx >> 1) * 8 + (lane & 7);
        oB[gi] = 12288 + nr * 48 + (mtx & 1) * 16;
    }

    float acc[2][4][4];
    #pragma unroll
    for (int i = 0; i < 2; i++)
        #pragma unroll
        for (int j = 0; j < 4; j++)
            #pragma unroll
            for (int k = 0; k < 4; k++) acc[i][j][k] = 0.f;

    #pragma unroll
    for (int sp = 0; sp < 2; sp++) {
        uint32_t sb = sbase + sp * STG_B;
        CP16(sb + adst, agh + sp * 16);
        CP16(sb + 6144 + adst, agl + sp * 16);
        CP16(sb + bdst, bgp + sp * 16);
        CPCOMMIT();
    }

    for (int c = 0; c < 64; c++) {
        if (c < 62) {
            int nc = c + 2;
            uint32_t sb = sbase + (nc % 3) * STG_B;
            CP16(sb + adst, agh + nc * 16);
            CP16(sb + 6144 + adst, agl + nc * 16);
            CP16(sb + bdst, bgp + nc * 16);
            CPCOMMIT();
            CPWAIT(2);
        } else if (c == 62) CPWAIT(1);
        else CPWAIT(0);
        __syncthreads();

        uint32_t sb = sbase + (c % 3) * STG_B;
        uint32_t Ahf[2][4], Alf[2][4], Bhf[2][4], Blf[2][4];
        #pragma unroll
        for (int ti = 0; ti < 2; ti++) {
            ldsm4(Ahf[ti][0], Ahf[ti][1], Ahf[ti][2], Ahf[ti][3], sb + oA[ti]);
            ldsm4(Alf[ti][0], Alf[ti][1], Alf[ti][2], Alf[ti][3], sb + 6144 + oA[ti]);
        }
        #pragma unroll
        for (int gi = 0; gi < 2; gi++) {
            ldsm4(Bhf[gi][0], Bhf[gi][1], Bhf[gi][2], Bhf[gi][3], sb + oB[gi]);
            ldsm4(Blf[gi][0], Blf[gi][1], Blf[gi][2], Blf[gi][3], sb + 3072 + oB[gi]);
        }
        #pragma unroll
        for (int ti = 0; ti < 2; ti++)
            #pragma unroll
            for (int gi = 0; gi < 2; gi++)
                #pragma unroll
                for (int sub = 0; sub < 2; sub++) {
                    int tn = gi * 2 + sub;
                    mma_bf16(acc[ti][tn], Ahf[ti], Bhf[gi][2 * sub], Bhf[gi][2 * sub + 1]);
                    mma_bf16(acc[ti][tn], Ahf[ti], Blf[gi][2 * sub], Blf[gi][2 * sub + 1]);
                    mma_bf16(acc[ti][tn], Alf[ti], Bhf[gi][2 * sub], Bhf[gi][2 * sub + 1]);
                }
        __syncthreads();
    }

    const int g = lane >> 2, tg = lane & 3;
    #pragma unroll
    for (int ti = 0; ti < 2; ti++) {
        int r0 = tM + m_idx * 32 + ti * 16 + g;
        #pragma unroll
        for (int tn = 0; tn < 4; tn++) {
            int col = tN + n_idx * 32 + tn * 8 + tg * 2;
            float b0 = bz[col], b1 = bz[col + 1];
            float v0 = acc[ti][tn][0] + b0, v1 = acc[ti][tn][1] + b1;
            float v2 = acc[ti][tn][2] + b0, v3 = acc[ti][tn][3] + b1;
            if (mode == 1) {
                v0 = 0.5f * v0 * (1.f + erff(v0 * 0.70710678118654752f));
                v1 = 0.5f * v1 * (1.f + erff(v1 * 0.70710678118654752f));
                v2 = 0.5f * v2 * (1.f + erff(v2 * 0.70710678118654752f));
                v3 = 0.5f * v3 * (1.f + erff(v3 * 0.70710678118654752f));
            }
            if (mode == 2) {
                uint32_t h, l;
                sp2(v0, v1, h, l);
                *(uint32_t*)(Ch + (size_t)z * sC + (size_t)r0 * ldc + col) = h;
                *(uint32_t*)(Cl + (size_t)z * sC + (size_t)r0 * ldc + col) = l;
                sp2(v2, v3, h, l);
                *(uint32_t*)(Ch + (size_t)z * sC + (size_t)(r0 + 8) * ldc + col) = h;
                *(uint32_t*)(Cl + (size_t)z * sC + (size_t)(r0 + 8) * ldc + col) = l;
            } else {
                float* Cz = Cf + (size_t)z * sC;
                *(float2*)(Cz + (size_t)r0 * ldc + col)       = make_float2(v0, v1);
                *(float2*)(Cz + (size_t)(r0 + 8) * ldc + col) = make_float2(v2, v3);
            }
        }
    }
}

// ---------------- LayerNorms ----------------
__global__ __launch_bounds__(256) void k_ln_row(const float* __restrict__ src,
                                                const float* __restrict__ g,
                                                const float* __restrict__ b,
                                                float* __restrict__ dst) {
    __shared__ float red[8];
    size_t row = blockIdx.x;
    int tid = threadIdx.x;
    float4 v = ((const float4*)src)[row * 256 + tid];
    float m = block_sum_256(v.x + v.y + v.z + v.w, red) * (1.f / 1024.f);
    float dx = v.x - m, dy = v.y - m, dz = v.z - m, dw = v.w - m;
    float var = block_sum_256(dx*dx + dy*dy + dz*dz + dw*dw, red) * (1.f / 1024.f);
    float rs = rsqrtf(var + 1e-5f);
    float4 gv = ((const float4*)g)[tid], bv = ((const float4*)b)[tid];
    float4 o;
    o.x = dx * rs * gv.x + bv.x; o.y = dy * rs * gv.y + bv.y;
    o.z = dz * rs * gv.z + bv.z; o.w = dw * rs * gv.w + bv.w;
    ((float4*)dst)[row * 256 + tid] = o;
}

__global__ __launch_bounds__(256) void k_ln_split(const float* __restrict__ src,
                                                  const float* __restrict__ g,
                                                  const float* __restrict__ b,
                                                  bf16* __restrict__ dh, bf16* __restrict__ dl) {
    __shared__ float red[8];
    size_t row = blockIdx.x;
    int tid = threadIdx.x;
    float4 v = ((const float4*)src)[row * 256 + tid];
    float m = block_sum_256(v.x + v.y + v.z + v.w, red) * (1.f / 1024.f);
    float dx = v.x - m, dy = v.y - m, dz = v.z - m, dw = v.w - m;
    float var = block_sum_256(dx*dx + dy*dy + dz*dz + dw*dw, red) * (1.f / 1024.f);
    float rs = rsqrtf(var + 1e-5f);
    float4 gv = ((const float4*)g)[tid], bv = ((const float4*)b)[tid];
    float o0 = dx * rs * gv.x + bv.x, o1 = dy * rs * gv.y + bv.y;
    float o2 = dz * rs * gv.z + bv.z, o3 = dw * rs * gv.w + bv.w;
    uint2 uh, ul;
    sp2(o0, o1, uh.x, ul.x);
    sp2(o2, o3, uh.y, ul.y);
    ((uint2*)dh)[row * 256 + tid] = uh;
    ((uint2*)dl)[row * 256 + tid] = ul;
}

__global__ __launch_bounds__(128) void k_qh(const float* __restrict__ chw, const float* __restrict__ chb,
                                            const float* __restrict__ tw, const float* __restrict__ tb) {
    int side = blockIdx.y;
    const float* W  = side ? tw : chw;
    const float* bb = side ? tb : chb;
    const float* q  = g_qln[side];
    __shared__ float qs[F_];
    int tid = threadIdx.x;
    for (int i = tid; i < F_; i += 128) qs[i] = q[i];
    __syncthreads();
    int j = blockIdx.x * 128 + tid;
    float a0 = 0.f, a1 = 0.f, a2 = 0.f, a3 = 0.f;
    for (int f = 0; f < F_; f += 4) {
        a0 = fmaf(qs[f], W[(size_t)f * C3F + j], a0);
        a1 = fmaf(qs[f + 1], W[(size_t)(f + 1) * C3F + j], a1);
        a2 = fmaf(qs[f + 2], W[(size_t)(f + 2) * C3F + j], a2);
        a3 = fmaf(qs[f + 3], W[(size_t)(f + 3) * C3F + j], a3);
    }
    g_qh[side][j] = a0 + a1 + a2 + a3 + bb[j];
}

__global__ __launch_bounds__(128) void k_fold(const float* __restrict__ chw, const float* __restrict__ chb,
                                              const float* __restrict__ tw, const float* __restrict__ tb) {
    int side = blockIdx.y, f = blockIdx.x, tid = threadIdx.x;
    const float* W  = side ? tw : chw;
    const float* qh = g_qh[side];
    __shared__ float wrow[F_];
    for (int i = tid; i < F_; i += 128) wrow[i] = W[(size_t)f * C3F + F_ + i];
    __syncthreads();
    int h = tid >> 3, i8 = tid & 7;
    float s = 0.f;
    #pragma unroll
    for (int d = 0; d < 8; d++) s += wrow[h * 64 + i8 * 8 + d] * qh[h * 64 + i8 * 8 + d];
    s += __shfl_down_sync(0xffffffffu, s, 4, 8);
    s += __shfl_down_sync(0xffffffffu, s, 2, 8);
    s += __shfl_down_sync(0xffffffffu, s, 1, 8);
    if (i8 == 0) g_wkeff[side][h * F_ + f] = s;
    if (f == 0 && tid < H_) {
        const float* bb = side ? tb : chb;
        float bs = 0.f;
        for (int d = 0; d < 64; d++) bs += bb[F_ + tid * 64 + d] * qh[tid * 64 + d];
        g_bkeff[side][tid] = bs;
    }
}

// ---------------- fused stage-1 v3 (proven) ----------------
#define SMEM_MAIN (D_ * F_ * 4 + 2 * 288 * 4 + 288 * 4 + 288 * 8)
__global__ __launch_bounds__(256) void k_main(const float* __restrict__ x) {
    extern __shared__ float sm[];
    float* xs   = sm;
    float* part = xs + D_ * F_;
    float* sc   = part + 2 * 288;
    u64* attnP  = (u64*)(sc + 288);

    int p = blockIdx.x, b = blockIdx.y, tid = threadIdx.x;
    int t = b * P_ + p;
    int w = tid >> 5, lane = tid & 31;
    int cg = w & 1, hg = w >> 1;

    ulonglong2 wk[4][4];
    #pragma unroll
    for (int hh = 0; hh < 4; hh++) {
        const ulonglong2* wr = (const ulonglong2*)(g_wkeff[0] + (hg * 4 + hh) * F_ + cg * 512);
        #pragma unroll
        for (int i = 0; i < 4; i++) wk[hh][i] = wr[lane + i * 32];
    }

    const float4* xg = (const float4*)x;
    #pragma unroll
    for (int k = 0; k < D_; k++)
        ((float4*)xs)[k * 256 + tid] = xg[((size_t)(b * D_ + k) * P_ + p) * 256 + tid];
    __syncthreads();

    for (int k = 0; k < D_; k++) {
        const ulonglong2* xr = (const ulonglong2*)(xs + k * F_ + cg * 512);
        ulonglong2 xv[4];
        #pragma unroll
        for (int i = 0; i < 4; i++) xv[i] = xr[lane + i * 32];
        #pragma unroll
        for (int hh = 0; hh < 4; hh++) {
            u64 s2 = 0;
            #pragma unroll
            for (int i = 0; i < 4; i++) {
                FMA2(s2, xv[i].x, wk[hh][i].x);
                FMA2(s2, xv[i].y, wk[hh][i].y);
            }
            float s = __uint_as_float((unsigned)s2) + __uint_as_float((unsigned)(s2 >> 32));
            #pragma unroll
            for (int o = 16; o; o >>= 1) s += __shfl_xor_sync(0xffffffffu, s, o);
            if (lane == 0) part[cg * 288 + (hg * 4 + hh) * D_ + k] = s;
        }
    }
    __syncthreads();

    for (int pair = tid; pair < 288; pair += 256)
        sc[pair] = (part[pair] + part[288 + pair] + g_bkeff[0][pair / D_]) * 0.125f;
    __syncthreads();

    if (tid < H_) {
        int h = tid;
        float mx = -1e30f;
        #pragma unroll
        for (int k = 0; k < D_; k++) mx = fmaxf(mx, sc[h * D_ + k]);
        float e[D_], ss = 0.f;
        #pragma unroll
        for (int k = 0; k < D_; k++) { e[k] = expf(sc[h * D_ + k] - mx); ss += e[k]; }
        float inv = 1.f / ss;
        #pragma unroll
        for (int k = 0; k < D_; k++) {
            unsigned u = __float_as_uint(e[k] * inv);
            attnP[k * H_ + h] = ((u64)u << 32) | u;
        }
    }
    __syncthreads();

    ulonglong2 acc2[H_];
    #pragma unroll
    for (int h = 0; h < H_; h++) { acc2[h].x = 0; acc2[h].y = 0; }
    #pragma unroll
    for (int k = 0; k < D_; k++) {
        ulonglong2 xv = ((const ulonglong2*)xs)[k * 256 + tid];
        const u64* ap = attnP + k * H_;
        #pragma unroll
        for (int h = 0; h < H_; h++) {
            u64 a = ap[h];
            FMA2(acc2[h].x, a, xv.x);
            FMA2(acc2[h].y, a, xv.y);
        }
    }
    #pragma unroll
    for (int h = 0; h < H_; h++) {
        float f0 = __uint_as_float((unsigned)acc2[h].x);
        float f1 = __uint_as_float((unsigned)(acc2[h].x >> 32));
        float f2 = __uint_as_float((unsigned)acc2[h].y);
        float f3 = __uint_as_float((unsigned)(acc2[h].y >> 32));
        uint2 uh, ul;
        sp2(f0, f1, uh.x, ul.x);
        sp2(f2, f3, uh.y, ul.y);
        size_t o = ((size_t)h * T_ + t) * 256 + tid;
        ((uint2*)g_mx_h)[o] = uh;
        ((uint2*)g_mx_l)[o] = ul;
    }
}

// ---------------- kv = ln(ln(z, cn), pnp) ----------------
__global__ __launch_bounds__(256) void k_lnln(const float* __restrict__ g1, const float* __restrict__ b1,
                                              const float* __restrict__ g2, const float* __restrict__ b2) {
    __shared__ float red[8];
    size_t row = blockIdx.x;
    int tid = threadIdx.x;
    float4 v = ((const float4*)g_z)[row * 256 + tid];
    float m = block_sum_256(v.x + v.y + v.z + v.w, red) * (1.f / 1024.f);
    float dx = v.x - m, dy = v.y - m, dz = v.z - m, dw = v.w - m;
    float var = block_sum_256(dx*dx + dy*dy + dz*dz + dw*dw, red) * (1.f / 1024.f);
    float rs = rsqrtf(var + 1e-5f);
    float4 g1v = ((const float4*)g1)[tid], b1v = ((const float4*)b1)[tid];
    float yx = dx * rs * g1v.x + b1v.x, yy = dy * rs * g1v.y + b1v.y;
    float yz = dz * rs * g1v.z + b1v.z, yw = dw * rs * g1v.w + b1v.w;
    float m2 = block_sum_256(yx + yy + yz + yw, red) * (1.f / 1024.f);
    float ex = yx - m2, ey = yy - m2, ez = yz - m2, ew = yw - m2;
    float var2 = block_sum_256(ex*ex + ey*ey + ez*ez + ew*ew, red) * (1.f / 1024.f);
    float rs2 = rsqrtf(var2 + 1e-5f);
    float4 g2v = ((const float4*)g2)[tid], b2v = ((const float4*)b2)[tid];
    float4 o;
    o.x = ex * rs2 * g2v.x + b2v.x; o.y = ey * rs2 * g2v.y + b2v.y;
    o.z = ez * rs2 * g2v.z + b2v.z; o.w = ew * rs2 * g2v.w + b2v.w;
    ((float4*)g_kv)[row * 256 + tid] = o;
}

// ---------------- stage-2 fused v2: smem-staged rows, warp-per-2-heads ----------------
__global__ __launch_bounds__(256) void k_sc2mix() {
    __shared__ float rows[4 * F_];     // 16 KB staging
    __shared__ float sc[H_ * P_];      // 4 KB scores
    int b = blockIdx.x, tid = threadIdx.x, w = tid >> 5, lane = tid & 31;

    // warp owns heads h0,h1; wkeff rows in registers
    int h0 = 2 * w, h1 = 2 * w + 1;
    ulonglong2 wk0[8], wk1[8];
    const ulonglong2* wr0 = (const ulonglong2*)(g_wkeff[1] + h0 * F_);
    const ulonglong2* wr1 = (const ulonglong2*)(g_wkeff[1] + h1 * F_);
    #pragma unroll
    for (int i = 0; i < 8; i++) { wk0[i] = wr0[lane + i * 32]; wk1[i] = wr1[lane + i * 32]; }
    float bk0 = g_bkeff[1][h0], bk1 = g_bkeff[1][h1];

    // score phase: stream kv rows through smem in batches of 4
    for (int pb = 0; pb < 16; pb++) {
        #pragma unroll
        for (int r = 0; r < 4; r++)
            ((float4*)rows)[r * 256 + tid] =
                ((const float4*)g_kv)[(size_t)(b * P_ + pb * 4 + r) * 256 + tid];
        __syncthreads();
        #pragma unroll
        for (int r = 0; r < 4; r++) {
            const ulonglong2* xr = (const ulonglong2*)(rows + r * F_);
            u64 s0 = 0, s1 = 0;
            #pragma unroll
            for (int i = 0; i < 8; i++) {
                ulonglong2 xv = xr[lane + i * 32];
                FMA2(s0, xv.x, wk0[i].x); FMA2(s0, xv.y, wk0[i].y);
                FMA2(s1, xv.x, wk1[i].x); FMA2(s1, xv.y, wk1[i].y);
            }
            float a0 = __uint_as_float((unsigned)s0) + __uint_as_float((unsigned)(s0 >> 32));
            float a1 = __uint_as_float((unsigned)s1) + __uint_as_float((unsigned)(s1 >> 32));
            #pragma unroll
            for (int o = 16; o; o >>= 1) {
                a0 += __shfl_xor_sync(0xffffffffu, a0, o);
                a1 += __shfl_xor_sync(0xffffffffu, a1, o);
            }
            if (lane == 0) {
                int p = pb * 4 + r;
                sc[h0 * P_ + p] = (a0 + bk0) * 0.125f;
                sc[h1 * P_ + p] = (a1 + bk1) * 0.125f;
            }
        }
        __syncthreads();
    }

    if (tid < H_) {
        int h = tid;
        float mx = -1e30f;
        for (int p = 0; p < P_; p++) mx = fmaxf(mx, sc[h * P_ + p]);
        float ss = 0.f;
        for (int p = 0; p < P_; p++) { float e = expf(sc[h * P_ + p] - mx); sc[h * P_ + p] = e; ss += e; }
        float inv = 1.f / ss;
        for (int p = 0; p < P_; p++) sc[h * P_ + p] *= inv;
    }
    __syncthreads();

    float4 acc[H_];
    #pragma unroll
    for (int h = 0; h < H_; h++) acc[h] = make_float4(0.f, 0.f, 0.f, 0.f);
    for (int p = 0; p < P_; p++) {
        float4 xv = ((const float4*)g_kv)[(size_t)(b * P_ + p) * 256 + tid];
        #pragma unroll
        for (int h = 0; h < H_; h++) {
            float a = sc[h * P_ + p];
            acc[h].x = fmaf(a, xv.x, acc[h].x); acc[h].y = fmaf(a, xv.y, acc[h].y);
            acc[h].z = fmaf(a, xv.z, acc[h].z); acc[h].w = fmaf(a, xv.w, acc[h].w);
        }
    }
    #pragma unroll
    for (int h = 0; h < H_; h++) {
        uint2 uh, ul;
        sp2(acc[h].x, acc[h].y, uh.x, ul.x);
        sp2(acc[h].z, acc[h].w, uh.y, ul.y);
        size_t o = (size_t)(h * B_ + b) * 256 + tid;
        ((uint2*)g_mx2_h)[o] = uh;
        ((uint2*)g_mx2_l)[o] = ul;
    }
}

__global__ __launch_bounds__(256) void k_logits(const float* __restrict__ w2,
                                                const float* __restrict__ b2,
                                                float* __restrict__ out) {
    int b = blockIdx.x, tid = threadIdx.x, w = tid >> 5, lane = tid & 31;
    const float* hrow = g_hid + (size_t)b * MH;
    for (int c = w; c < NC; c += 8) {
        float s = 0.f;
        for (int i = lane; i < MH; i += 32) s = fmaf(hrow[i], w2[(size_t)i * NC + c], s);
        #pragma unroll
        for (int o = 16; o; o >>= 1) s += __shfl_xor_sync(0xffffffffu, s, o);
        if (lane == 0) out[b * NC + c] = s + b2[c];
    }
}

// ---------------- launch ----------------
extern "C" void kernel_launch(void* const* d_in, const int* in_sizes, int n_in,
                              void* d_out, int out_size) {
    (void)in_sizes; (void)n_in; (void)out_size;
    const float* x    = (const float*)d_in[0];
    const float* chq  = (const float*)d_in[1];
    const float* clq  = (const float*)d_in[2];
    const float* chw  = (const float*)d_in[3];
    const float* chb  = (const float*)d_in[4];
    const float* chow = (const float*)d_in[5];
    const float* chob = (const float*)d_in[6];
    const float* tw   = (const float*)d_in[7];
    const float* tb   = (const float*)d_in[8];
    const float* tow  = (const float*)d_in[9];
    const float* tob  = (const float*)d_in[10];
    const float* qn_g = (const float*)d_in[11];
    const float* qn_b = (const float*)d_in[12];
    const float* cn_g = (const float*)d_in[13];
    const float* cn_b = (const float*)d_in[14];
    const float* pnc_g = (const float*)d_in[15];
    const float* pnc_b = (const float*)d_in[16];
    const float* pnp_g = (const float*)d_in[17];
    const float* pnp_b = (const float*)d_in[18];
    const float* pon_g = (const float*)d_in[19];
    const float* pon_b = (const float*)d_in[20];
    const float* w1 = (const float*)d_in[21];
    const float* b1 = (const float*)d_in[22];
    const float* w2 = (const float*)d_in[23];
    const float* b2 = (const float*)d_in[24];
    float* out = (float*)d_out;

    float *p_qln, *p_z, *p_p2, *p_hid;
    bf16 *mxh, *mxl, *plh, *pll, *m2h, *m2l, *p2h, *p2l, *lnh, *lnl;
    bf16 *wvh, *wvl, *cwh, *cwl, *w2h, *w2l, *toh, *tol, *w1h, *w1l;
    cudaGetSymbolAddress((void**)&p_qln, g_qln);
    cudaGetSymbolAddress((void**)&p_z, g_z);
    cudaGetSymbolAddress((void**)&p_p2, g_p2);
    cudaGetSymbolAddress((void**)&p_hid, g_hid);
    cudaGetSymbolAddress((void**)&mxh, g_mx_h);     cudaGetSymbolAddress((void**)&mxl, g_mx_l);
    cudaGetSymbolAddress((void**)&plh, g_pooled_h); cudaGetSymbolAddress((void**)&pll, g_pooled_l);
    cudaGetSymbolAddress((void**)&m2h, g_mx2_h);    cudaGetSymbolAddress((void**)&m2l, g_mx2_l);
    cudaGetSymbolAddress((void**)&p2h, g_pooled2_h);cudaGetSymbolAddress((void**)&p2l, g_pooled2_l);
    cudaGetSymbolAddress((void**)&lnh, g_p2ln_h);   cudaGetSymbolAddress((void**)&lnl, g_p2ln_l);
    cudaGetSymbolAddress((void**)&wvh, g_wvT_h);    cudaGetSymbolAddress((void**)&wvl, g_wvT_l);
    cudaGetSymbolAddress((void**)&cwh, g_chowT_h);  cudaGetSymbolAddress((void**)&cwl, g_chowT_l);
    cudaGetSymbolAddress((void**)&w2h, g_wv2T_h);   cudaGetSymbolAddress((void**)&w2l, g_wv2T_l);
    cudaGetSymbolAddress((void**)&toh, g_towT_h);   cudaGetSymbolAddress((void**)&tol, g_towT_l);
    cudaGetSymbolAddress((void**)&w1h, g_w1T_h);    cudaGetSymbolAddress((void**)&w1l, g_w1T_l);

    cudaFuncSetAttribute(k_main, cudaFuncAttributeMaxDynamicSharedMemorySize, SMEM_MAIN);
    cudaFuncSetAttribute(k_mma, cudaFuncAttributeMaxDynamicSharedMemorySize, 3 * STG_B);
    const int MMS = 3 * STG_B;

    // reordered so launch index 5 = k_main (for ncu -s 5 -c 1)
    k_trsplit<<<dim3(32, 32), 256>>>(chw, C3F, 2 * F_, wvh, wvl);          // 0
    k_ln_row<<<1, 256>>>(chq, qn_g, qn_b, p_qln);                           // 1
    k_ln_row<<<1, 256>>>(clq, pnc_g, pnc_b, p_qln + F_);                    // 2
    k_qh<<<dim3(8, 2), 128>>>(chw, chb, tw, tb);                            // 3
    k_fold<<<dim3(1024, 2), 128>>>(chw, chb, tw, tb);                       // 4
    k_main<<<dim3(P_, B_), 256, SMEM_MAIN>>>(x);                            // 5 <- profiled
    k_mma<<<dim3(1, T_ / 128, H_), 256, MMS>>>(mxh, mxl, (long long)T_ * F_,
        wvh, wvl, (long long)64 * F_, chb + 2 * F_, 64,
        nullptr, plh, pll, F_, 64, 2);                                      // 6
    k_trsplit<<<dim3(32, 32), 256>>>(chow, F_, 0, cwh, cwl);                // 7
    k_mma<<<dim3(F_ / 64, T_ / 128, 1), 256, MMS>>>(plh, pll, 0,
        cwh, cwl, 0, chob, 0, p_z, nullptr, nullptr, F_, 0, 0);             // 8
    k_lnln<<<T_, 256>>>(cn_g, cn_b, pnp_g, pnp_b);                          // 9
    k_sc2mix<<<B_, 256>>>();                                                // 10
    k_trsplit<<<dim3(32, 32), 256>>>(tw, C3F, 2 * F_, w2h, w2l);            // 11
    k_mma<<<dim3(1, 1, H_), 256, MMS>>>(m2h, m2l, (long long)B_ * F_,
        w2h, w2l, (long long)64 * F_, tb + 2 * F_, 64,
        nullptr, p2h, p2l, F_, 64, 2);                                      // 12
    k_trsplit<<<dim3(32, 32), 256>>>(tow, F_, 0, toh, tol);                 // 13
    k_mma<<<dim3(F_ / 64, 1, 1), 256, MMS>>>(p2h, p2l, 0,
        toh, tol, 0, tob, 0, p_p2, nullptr, nullptr, F_, 0, 0);             // 14
    k_ln_split<<<B_, 256>>>(p_p2, pon_g, pon_b, lnh, lnl);                  // 15
    k_trsplit<<<dim3(32, 128), 256>>>(w1, MH, 0, w1h, w1l);                 // 16
    k_mma<<<dim3(MH / 64, 1, 1), 256, MMS>>>(lnh, lnl, 0,
        w1h, w1l, 0, b1, 0, p_hid, nullptr, nullptr, MH, 0, 1);             // 17
    k_logits<<<B_, 256>>>(w2, b2, out);                                     // 18
}

// round 16
// speedup vs baseline: 2.2264x; 1.0785x over previous
#include <cuda_runtime.h>
#include <cuda_bf16.h>
#include <math.h>
#include <stdint.h>

#define F_  1024
#define H_  16
#define D_  18
#define P_  64
#define B_  128
#define T_  8192
#define C3F 3072
#define NC  23
#define MH  4096

typedef __nv_bfloat16 bf16;
typedef unsigned long long u64;

__device__ float g_qln[2][F_];
__device__ float g_qhp[2][8][F_];
__device__ __align__(16) float g_wkeff[2][H_ * F_];
__device__ float g_bkeff[2][H_];
__device__ float g_z[(size_t)T_ * F_];
__device__ float g_kv[(size_t)T_ * F_];
__device__ float g_p2[B_ * F_];
__device__ float g_hid[B_ * MH];
__device__ __align__(16) bf16 g_mx_h[(size_t)H_ * T_ * F_], g_mx_l[(size_t)H_ * T_ * F_];
__device__ __align__(16) bf16 g_pooled_h[(size_t)T_ * F_], g_pooled_l[(size_t)T_ * F_];
__device__ __align__(16) bf16 g_mx2_h[H_ * B_ * F_], g_mx2_l[H_ * B_ * F_];
__device__ __align__(16) bf16 g_pooled2_h[B_ * F_], g_pooled2_l[B_ * F_];
__device__ __align__(16) bf16 g_p2ln_h[B_ * F_], g_p2ln_l[B_ * F_];
__device__ __align__(16) bf16 g_wvT_h[F_ * F_],  g_wvT_l[F_ * F_];
__device__ __align__(16) bf16 g_chowT_h[F_ * F_], g_chowT_l[F_ * F_];
__device__ __align__(16) bf16 g_wv2T_h[F_ * F_], g_wv2T_l[F_ * F_];
__device__ __align__(16) bf16 g_towT_h[F_ * F_], g_towT_l[F_ * F_];
__device__ __align__(16) bf16 g_w1T_h[MH * F_],  g_w1T_l[MH * F_];

__device__ __forceinline__ uint32_t smem_u32(const void* p) {
    uint32_t a;
    asm("{ .reg .u64 t; cvta.to.shared.u64 t, %1; cvt.u32.u64 %0, t; }" : "=r"(a) : "l"(p));
    return a;
}
__device__ __forceinline__ void ldsm4(uint32_t& r0, uint32_t& r1, uint32_t& r2, uint32_t& r3, uint32_t a) {
    asm volatile("ldmatrix.sync.aligned.m8n8.x4.shared.b16 {%0,%1,%2,%3}, [%4];"
        : "=r"(r0), "=r"(r1), "=r"(r2), "=r"(r3) : "r"(a));
}
__device__ __forceinline__ void mma_bf16(float* c, const uint32_t* a, uint32_t b0, uint32_t b1) {
    asm volatile("mma.sync.aligned.m16n8k16.row.col.f32.bf16.bf16.f32 "
        "{%0,%1,%2,%3},{%4,%5,%6,%7},{%8,%9},{%0,%1,%2,%3};"
        : "+f"(c[0]), "+f"(c[1]), "+f"(c[2]), "+f"(c[3])
        : "r"(a[0]), "r"(a[1]), "r"(a[2]), "r"(a[3]), "r"(b0), "r"(b1));
}
#define CP16(dst, src) asm volatile("cp.async.cg.shared.global [%0], [%1], 16;" :: "r"(dst), "l"(src))
#define CPCOMMIT()     asm volatile("cp.async.commit_group;" ::: "memory")
#define CPWAIT(n)      asm volatile("cp.async.wait_group %0;" :: "n"(n) : "memory")
#define FMA2(d, a, b)  asm("fma.rn.f32x2 %0, %1, %2, %0;" : "+l"(d) : "l"(a), "l"(b))

__device__ __forceinline__ void sp2(float v0, float v1, uint32_t& h, uint32_t& l) {
    bf16 h0 = __float2bfloat16(v0), h1 = __float2bfloat16(v1);
    bf16 l0 = __float2bfloat16(v0 - __bfloat162float(h0));
    bf16 l1 = __float2bfloat16(v1 - __bfloat162float(h1));
    h = ((uint32_t)__bfloat16_as_ushort(h1) << 16) | __bfloat16_as_ushort(h0);
    l = ((uint32_t)__bfloat16_as_ushort(l1) << 16) | __bfloat16_as_ushort(l0);
}
__device__ __forceinline__ float block_sum_256(float v, float* red) {
    #pragma unroll
    for (int o = 16; o; o >>= 1) v += __shfl_xor_sync(0xffffffffu, v, o);
    int w = threadIdx.x >> 5;
    if ((threadIdx.x & 31) == 0) red[w] = v;
    __syncthreads();
    float s = red[0];
    #pragma unroll
    for (int i = 1; i < 8; i++) s += red[i];
    __syncthreads();
    return s;
}

// ---------------- weight transpose + split ----------------
__global__ __launch_bounds__(256) void k_trsplit(const float* __restrict__ src, int lds, int ofs,
                                                 bf16* __restrict__ dh, bf16* __restrict__ dl) {
    __shared__ float t[32][33];
    int k0 = blockIdx.x * 32, n0 = blockIdx.y * 32;
    int tx = threadIdx.x & 31, ty = threadIdx.x >> 5;
    #pragma unroll
    for (int j = 0; j < 4; j++)
        t[ty + j * 8][tx] = src[(size_t)(k0 + ty + j * 8) * lds + ofs + n0 + tx];
    __syncthreads();
    #pragma unroll
    for (int j = 0; j < 4; j++) {
        int r = ty + j * 8;
        float v = t[tx][r];
        bf16 h = __float2bfloat16(v);
        bf16 l = __float2bfloat16(v - __bfloat162float(h));
        size_t o = (size_t)(n0 + r) * F_ + k0 + tx;
        dh[o] = h; dl[o] = l;
    }
}

// ---------------- cp.async 3-stage split-bf16 GEMM (proven) ----------------
#define STG_B 18432
__global__ __launch_bounds__(256) void k_mma(
    const bf16* __restrict__ Ah, const bf16* __restrict__ Al, long long sA,
    const bf16* __restrict__ Bh, const bf16* __restrict__ Bl, long long sB,
    const float* __restrict__ bias, long long sBias,
    float* __restrict__ Cf, bf16* __restrict__ Ch, bf16* __restrict__ Cl,
    int ldc, long long sC, int mode)
{
    extern __shared__ bf16 s[];
    int z = blockIdx.z;
    Ah += (size_t)z * sA; Al += (size_t)z * sA;
    Bh += (size_t)z * sB; Bl += (size_t)z * sB;
    const float* bz = bias + (size_t)z * sBias;
    const int tM = blockIdx.y * 128, tN = blockIdx.x * 64;
    const int t = threadIdx.x, wid = t >> 5, lane = t & 31;
    const int m_idx = wid >> 1, n_idx = wid & 1;
    uint32_t sbase = smem_u32(s);

    const int ar = t >> 1, aseg = t & 1;
    const bf16* agh = Ah + (size_t)(tM + ar) * F_ + aseg * 8;
    const bf16* agl = Al + (size_t)(tM + ar) * F_ + aseg * 8;
    const uint32_t adst = ar * 48 + aseg * 16;
    const int br = (t & 127) >> 1, bseg = t & 1;
    const bf16* bgp = ((t < 128) ? Bh : Bl) + (size_t)(tN + br) * F_ + bseg * 8;
    const uint32_t bdst = 12288 + ((t >= 128) ? 3072u : 0u) + br * 48 + bseg * 16;

    uint32_t oA[2], oB[2];
    #pragma unroll
    for (int ti = 0; ti < 2; ti++) {
        int r = m_idx * 32 + ti * 16 + (lane & 15);
        oA[ti] = r * 48 + (lane >> 4) * 16;
    }
    #pragma unroll
    for (int gi = 0; gi < 2; gi++) {
        int mtx = lane >> 3;
        int nr = n_idx * 32 + gi * 16 + (mtx >> 1) * 8 + (lane & 7);
        oB[gi] = 12288 + nr * 48 + (mtx & 1) * 16;
    }

    float acc[2][4][4];
    #pragma unroll
    for (int i = 0; i < 2; i++)
        #pragma unroll
        for (int j = 0; j < 4; j++)
            #pragma unroll
            for (int k = 0; k < 4; k++) acc[i][j][k] = 0.f;

    #pragma unroll
    for (int sp = 0; sp < 2; sp++) {
        uint32_t sb = sbase + sp * STG_B;
        CP16(sb + adst, agh + sp * 16);
        CP16(sb + 6144 + adst, agl + sp * 16);
        CP16(sb + bdst, bgp + sp * 16);
        CPCOMMIT();
    }

    for (int c = 0; c < 64; c++) {
        if (c < 62) {
            int nc = c + 2;
            uint32_t sb = sbase + (nc % 3) * STG_B;
            CP16(sb + adst, agh + nc * 16);
            CP16(sb + 6144 + adst, agl + nc * 16);
            CP16(sb + bdst, bgp + nc * 16);
            CPCOMMIT();
            CPWAIT(2);
        } else if (c == 62) CPWAIT(1);
        else CPWAIT(0);
        __syncthreads();

        uint32_t sb = sbase + (c % 3) * STG_B;
        uint32_t Ahf[2][4], Alf[2][4], Bhf[2][4], Blf[2][4];
        #pragma unroll
        for (int ti = 0; ti < 2; ti++) {
            ldsm4(Ahf[ti][0], Ahf[ti][1], Ahf[ti][2], Ahf[ti][3], sb + oA[ti]);
            ldsm4(Alf[ti][0], Alf[ti][1], Alf[ti][2], Alf[ti][3], sb + 6144 + oA[ti]);
        }
        #pragma unroll
        for (int gi = 0; gi < 2; gi++) {
            ldsm4(Bhf[gi][0], Bhf[gi][1], Bhf[gi][2], Bhf[gi][3], sb + oB[gi]);
            ldsm4(Blf[gi][0], Blf[gi][1], Blf[gi][2], Blf[gi][3], sb + 3072 + oB[gi]);
        }
        #pragma unroll
        for (int ti = 0; ti < 2; ti++)
            #pragma unroll
            for (int gi = 0; gi < 2; gi++)
                #pragma unroll
                for (int sub = 0; sub < 2; sub++) {
                    int tn = gi * 2 + sub;
                    mma_bf16(acc[ti][tn], Ahf[ti], Bhf[gi][2 * sub], Bhf[gi][2 * sub + 1]);
                    mma_bf16(acc[ti][tn], Ahf[ti], Blf[gi][2 * sub], Blf[gi][2 * sub + 1]);
                    mma_bf16(acc[ti][tn], Alf[ti], Bhf[gi][2 * sub], Bhf[gi][2 * sub + 1]);
                }
        __syncthreads();
    }

    const int g = lane >> 2, tg = lane & 3;
    #pragma unroll
    for (int ti = 0; ti < 2; ti++) {
        int r0 = tM + m_idx * 32 + ti * 16 + g;
        #pragma unroll
        for (int tn = 0; tn < 4; tn++) {
            int col = tN + n_idx * 32 + tn * 8 + tg * 2;
            float b0 = bz[col], b1 = bz[col + 1];
            float v0 = acc[ti][tn][0] + b0, v1 = acc[ti][tn][1] + b1;
            float v2 = acc[ti][tn][2] + b0, v3 = acc[ti][tn][3] + b1;
            if (mode == 1) {
                v0 = 0.5f * v0 * (1.f + erff(v0 * 0.70710678118654752f));
                v1 = 0.5f * v1 * (1.f + erff(v1 * 0.70710678118654752f));
                v2 = 0.5f * v2 * (1.f + erff(v2 * 0.70710678118654752f));
                v3 = 0.5f * v3 * (1.f + erff(v3 * 0.70710678118654752f));
            }
            if (mode == 2) {
                uint32_t h, l;
                sp2(v0, v1, h, l);
                *(uint32_t*)(Ch + (size_t)z * sC + (size_t)r0 * ldc + col) = h;
                *(uint32_t*)(Cl + (size_t)z * sC + (size_t)r0 * ldc + col) = l;
                sp2(v2, v3, h, l);
                *(uint32_t*)(Ch + (size_t)z * sC + (size_t)(r0 + 8) * ldc + col) = h;
                *(uint32_t*)(Cl + (size_t)z * sC + (size_t)(r0 + 8) * ldc + col) = l;
            } else {
                float* Cz = Cf + (size_t)z * sC;
                *(float2*)(Cz + (size_t)r0 * ldc + col)       = make_float2(v0, v1);
                *(float2*)(Cz + (size_t)(r0 + 8) * ldc + col) = make_float2(v2, v3);
            }
        }
    }
}

// ---------------- merged query LayerNorm (grid 2) ----------------
__global__ __launch_bounds__(256) void k_lnq(const float* __restrict__ chq, const float* __restrict__ clq,
                                             const float* __restrict__ g0, const float* __restrict__ b0,
                                             const float* __restrict__ g1, const float* __restrict__ b1) {
    __shared__ float red[8];
    int which = blockIdx.x;
    const float* src = which ? clq : chq;
    const float* g = which ? g1 : g0;
    const float* b = which ? b1 : b0;
    float* dst = g_qln[which];
    int tid = threadIdx.x;
    float4 v = ((const float4*)src)[tid];
    float m = block_sum_256(v.x + v.y + v.z + v.w, red) * (1.f / 1024.f);
    float dx = v.x - m, dy = v.y - m, dz = v.z - m, dw = v.w - m;
    float var = block_sum_256(dx*dx + dy*dy + dz*dz + dw*dw, red) * (1.f / 1024.f);
    float rs = rsqrtf(var + 1e-5f);
    float4 gv = ((const float4*)g)[tid], bv = ((const float4*)b)[tid];
    float4 o;
    o.x = dx * rs * gv.x + bv.x; o.y = dy * rs * gv.y + bv.y;
    o.z = dz * rs * gv.z + bv.z; o.w = dw * rs * gv.w + bv.w;
    ((float4*)dst)[tid] = o;
}

__global__ __launch_bounds__(256) void k_ln_split(const float* __restrict__ src,
                                                  const float* __restrict__ g,
                                                  const float* __restrict__ b,
                                                  bf16* __restrict__ dh, bf16* __restrict__ dl) {
    __shared__ float red[8];
    size_t row = blockIdx.x;
    int tid = threadIdx.x;
    float4 v = ((const float4*)src)[row * 256 + tid];
    float m = block_sum_256(v.x + v.y + v.z + v.w, red) * (1.f / 1024.f);
    float dx = v.x - m, dy = v.y - m, dz = v.z - m, dw = v.w - m;
    float var = block_sum_256(dx*dx + dy*dy + dz*dz + dw*dw, red) * (1.f / 1024.f);
    float rs = rsqrtf(var + 1e-5f);
    float4 gv = ((const float4*)g)[tid], bv = ((const float4*)b)[tid];
    float o0 = dx * rs * gv.x + bv.x, o1 = dy * rs * gv.y + bv.y;
    float o2 = dz * rs * gv.z + bv.z, o3 = dw * rs * gv.w + bv.w;
    uint2 uh, ul;
    sp2(o0, o1, uh.x, ul.x);
    sp2(o2, o3, uh.y, ul.y);
    ((uint2*)dh)[row * 256 + tid] = uh;
    ((uint2*)dl)[row * 256 + tid] = ul;
}

// ---------------- qh partials: split-K over grid.z ----------------
__global__ __launch_bounds__(128) void k_qh(const float* __restrict__ chw, const float* __restrict__ tw) {
    int side = blockIdx.y, ks = blockIdx.z;
    const float* W = side ? tw : chw;
    const float* q = g_qln[side] + ks * 128;
    __shared__ float qs[128];
    int tid = threadIdx.x;
    qs[tid] = q[tid];
    __syncthreads();
    int j = blockIdx.x * 128 + tid;
    const float* Wp = W + (size_t)(ks * 128) * C3F + j;
    float a0 = 0.f, a1 = 0.f, a2 = 0.f, a3 = 0.f;
    for (int f = 0; f < 128; f += 4) {
        a0 = fmaf(qs[f],     Wp[(size_t)f * C3F], a0);
        a1 = fmaf(qs[f + 1], Wp[(size_t)(f + 1) * C3F], a1);
        a2 = fmaf(qs[f + 2], Wp[(size_t)(f + 2) * C3F], a2);
        a3 = fmaf(qs[f + 3], Wp[(size_t)(f + 3) * C3F], a3);
    }
    g_qhp[side][ks][j] = a0 + a1 + a2 + a3;
}

// ---------------- fold (2 f-rows per block, reduces qh partials inline) ----------------
__global__ __launch_bounds__(128) void k_fold(const float* __restrict__ chw, const float* __restrict__ chb,
                                              const float* __restrict__ tw, const float* __restrict__ tb) {
    int side = blockIdx.y, f0 = blockIdx.x * 2, tid = threadIdx.x;
    const float* W  = side ? tw : chw;
    const float* bb = side ? tb : chb;
    __shared__ float qh[F_];
    __shared__ float wrow[2][F_];
    for (int i = tid; i < F_; i += 128) {
        float s = bb[i];
        #pragma unroll
        for (int ks = 0; ks < 8; ks++) s += g_qhp[side][ks][i];
        qh[i] = s;
    }
    for (int i = tid; i < F_; i += 128) {
        wrow[0][i] = W[(size_t)f0 * C3F + F_ + i];
        wrow[1][i] = W[(size_t)(f0 + 1) * C3F + F_ + i];
    }
    __syncthreads();
    int h = tid >> 3, i8 = tid & 7;
    #pragma unroll
    for (int r = 0; r < 2; r++) {
        float s = 0.f;
        #pragma unroll
        for (int d = 0; d < 8; d++) s += wrow[r][h * 64 + i8 * 8 + d] * qh[h * 64 + i8 * 8 + d];
        s += __shfl_down_sync(0xffffffffu, s, 4, 8);
        s += __shfl_down_sync(0xffffffffu, s, 2, 8);
        s += __shfl_down_sync(0xffffffffu, s, 1, 8);
        if (i8 == 0) g_wkeff[side][h * F_ + f0 + r] = s;
    }
    if (f0 == 0 && tid < H_) {
        float bs = 0.f;
        for (int d = 0; d < 64; d++) bs += bb[F_ + tid * 64 + d] * qh[tid * 64 + d];
        g_bkeff[side][tid] = bs;
    }
}

// ---------------- fused stage-1 v3 (proven) ----------------
#define SMEM_MAIN (D_ * F_ * 4 + 2 * 288 * 4 + 288 * 4 + 288 * 8)
__global__ __launch_bounds__(256) void k_main(const float* __restrict__ x) {
    extern __shared__ float sm[];
    float* xs   = sm;
    float* part = xs + D_ * F_;
    float* sc   = part + 2 * 288;
    u64* attnP  = (u64*)(sc + 288);

    int p = blockIdx.x, b = blockIdx.y, tid = threadIdx.x;
    int t = b * P_ + p;
    int w = tid >> 5, lane = tid & 31;
    int cg = w & 1, hg = w >> 1;

    ulonglong2 wk[4][4];
    #pragma unroll
    for (int hh = 0; hh < 4; hh++) {
        const ulonglong2* wr = (const ulonglong2*)(g_wkeff[0] + (hg * 4 + hh) * F_ + cg * 512);
        #pragma unroll
        for (int i = 0; i < 4; i++) wk[hh][i] = wr[lane + i * 32];
    }

    const float4* xg = (const float4*)x;
    #pragma unroll
    for (int k = 0; k < D_; k++)
        ((float4*)xs)[k * 256 + tid] = xg[((size_t)(b * D_ + k) * P_ + p) * 256 + tid];
    __syncthreads();

    for (int k = 0; k < D_; k++) {
        const ulonglong2* xr = (const ulonglong2*)(xs + k * F_ + cg * 512);
        ulonglong2 xv[4];
        #pragma unroll
        for (int i = 0; i < 4; i++) xv[i] = xr[lane + i * 32];
        #pragma unroll
        for (int hh = 0; hh < 4; hh++) {
            u64 s2 = 0;
            #pragma unroll
            for (int i = 0; i < 4; i++) {
                FMA2(s2, xv[i].x, wk[hh][i].x);
                FMA2(s2, xv[i].y, wk[hh][i].y);
            }
            float s = __uint_as_float((unsigned)s2) + __uint_as_float((unsigned)(s2 >> 32));
            #pragma unroll
            for (int o = 16; o; o >>= 1) s += __shfl_xor_sync(0xffffffffu, s, o);
            if (lane == 0) part[cg * 288 + (hg * 4 + hh) * D_ + k] = s;
        }
    }
    __syncthreads();

    for (int pair = tid; pair < 288; pair += 256)
        sc[pair] = (part[pair] + part[288 + pair] + g_bkeff[0][pair / D_]) * 0.125f;
    __syncthreads();

    if (tid < H_) {
        int h = tid;
        float mx = -1e30f;
        #pragma unroll
        for (int k = 0; k < D_; k++) mx = fmaxf(mx, sc[h * D_ + k]);
        float e[D_], ss = 0.f;
        #pragma unroll
        for (int k = 0; k < D_; k++) { e[k] = expf(sc[h * D_ + k] - mx); ss += e[k]; }
        float inv = 1.f / ss;
        #pragma unroll
        for (int k = 0; k < D_; k++) {
            unsigned u = __float_as_uint(e[k] * inv);
            attnP[k * H_ + h] = ((u64)u << 32) | u;
        }
    }
    __syncthreads();

    ulonglong2 acc2[H_];
    #pragma unroll
    for (int h = 0; h < H_; h++) { acc2[h].x = 0; acc2[h].y = 0; }
    #pragma unroll
    for (int k = 0; k < D_; k++) {
        ulonglong2 xv = ((const ulonglong2*)xs)[k * 256 + tid];
        const u64* ap = attnP + k * H_;
        #pragma unroll
        for (int h = 0; h < H_; h++) {
            u64 a = ap[h];
            FMA2(acc2[h].x, a, xv.x);
            FMA2(acc2[h].y, a, xv.y);
        }
    }
    #pragma unroll
    for (int h = 0; h < H_; h++) {
        float f0 = __uint_as_float((unsigned)acc2[h].x);
        float f1 = __uint_as_float((unsigned)(acc2[h].x >> 32));
        float f2 = __uint_as_float((unsigned)acc2[h].y);
        float f3 = __uint_as_float((unsigned)(acc2[h].y >> 32));
        uint2 uh, ul;
        sp2(f0, f1, uh.x, ul.x);
        sp2(f2, f3, uh.y, ul.y);
        size_t o = ((size_t)h * T_ + t) * 256 + tid;
        ((uint2*)g_mx_h)[o] = uh;
        ((uint2*)g_mx_l)[o] = ul;
    }
}

// ---------------- kv = ln(ln(z, cn), pnp) ----------------
__global__ __launch_bounds__(256) void k_lnln(const float* __restrict__ g1, const float* __restrict__ b1,
                                              const float* __restrict__ g2, const float* __restrict__ b2) {
    __shared__ float red[8];
    size_t row = blockIdx.x;
    int tid = threadIdx.x;
    float4 v = ((const float4*)g_z)[row * 256 + tid];
    float m = block_sum_256(v.x + v.y + v.z + v.w, red) * (1.f / 1024.f);
    float dx = v.x - m, dy = v.y - m, dz = v.z - m, dw = v.w - m;
    float var = block_sum_256(dx*dx + dy*dy + dz*dz + dw*dw, red) * (1.f / 1024.f);
    float rs = rsqrtf(var + 1e-5f);
    float4 g1v = ((const float4*)g1)[tid], b1v = ((const float4*)b1)[tid];
    float yx = dx * rs * g1v.x + b1v.x, yy = dy * rs * g1v.y + b1v.y;
    float yz = dz * rs * g1v.z + b1v.z, yw = dw * rs * g1v.w + b1v.w;
    float m2 = block_sum_256(yx + yy + yz + yw, red) * (1.f / 1024.f);
    float ex = yx - m2, ey = yy - m2, ez = yz - m2, ew = yw - m2;
    float var2 = block_sum_256(ex*ex + ey*ey + ez*ez + ew*ew, red) * (1.f / 1024.f);
    float rs2 = rsqrtf(var2 + 1e-5f);
    float4 g2v = ((const float4*)g2)[tid], b2v = ((const float4*)b2)[tid];
    float4 o;
    o.x = ex * rs2 * g2v.x + b2v.x; o.y = ey * rs2 * g2v.y + b2v.y;
    o.z = ez * rs2 * g2v.z + b2v.z; o.w = ew * rs2 * g2v.w + b2v.w;
    ((float4*)g_kv)[row * 256 + tid] = o;
}

// ---------------- stage-2 fused v2 ----------------
__global__ __launch_bounds__(256) void k_sc2mix() {
    __shared__ float rows[4 * F_];
    __shared__ float sc[H_ * P_];
    int b = blockIdx.x, tid = threadIdx.x, w = tid >> 5, lane = tid & 31;

    int h0 = 2 * w, h1 = 2 * w + 1;
    ulonglong2 wk0[8], wk1[8];
    const ulonglong2* wr0 = (const ulonglong2*)(g_wkeff[1] + h0 * F_);
    const ulonglong2* wr1 = (const ulonglong2*)(g_wkeff[1] + h1 * F_);
    #pragma unroll
    for (int i = 0; i < 8; i++) { wk0[i] = wr0[lane + i * 32]; wk1[i] = wr1[lane + i * 32]; }
    float bk0 = g_bkeff[1][h0], bk1 = g_bkeff[1][h1];

    for (int pb = 0; pb < 16; pb++) {
        #pragma unroll
        for (int r = 0; r < 4; r++)
            ((float4*)rows)[r * 256 + tid] =
                ((const float4*)g_kv)[(size_t)(b * P_ + pb * 4 + r) * 256 + tid];
        __syncthreads();
        #pragma unroll
        for (int r = 0; r < 4; r++) {
            const ulonglong2* xr = (const ulonglong2*)(rows + r * F_);
            u64 s0 = 0, s1 = 0;
            #pragma unroll
            for (int i = 0; i < 8; i++) {
                ulonglong2 xv = xr[lane + i * 32];
                FMA2(s0, xv.x, wk0[i].x); FMA2(s0, xv.y, wk0[i].y);
                FMA2(s1, xv.x, wk1[i].x); FMA2(s1, xv.y, wk1[i].y);
            }
            float a0 = __uint_as_float((unsigned)s0) + __uint_as_float((unsigned)(s0 >> 32));
            float a1 = __uint_as_float((unsigned)s1) + __uint_as_float((unsigned)(s1 >> 32));
            #pragma unroll
            for (int o = 16; o; o >>= 1) {
                a0 += __shfl_xor_sync(0xffffffffu, a0, o);
                a1 += __shfl_xor_sync(0xffffffffu, a1, o);
            }
            if (lane == 0) {
                int p = pb * 4 + r;
                sc[h0 * P_ + p] = (a0 + bk0) * 0.125f;
                sc[h1 * P_ + p] = (a1 + bk1) * 0.125f;
            }
        }
        __syncthreads();
    }

    if (tid < H_) {
        int h = tid;
        float mx = -1e30f;
        for (int p = 0; p < P_; p++) mx = fmaxf(mx, sc[h * P_ + p]);
        float ss = 0.f;
        for (int p = 0; p < P_; p++) { float e = expf(sc[h * P_ + p] - mx); sc[h * P_ + p] = e; ss += e; }
        float inv = 1.f / ss;
        for (int p = 0; p < P_; p++) sc[h * P_ + p] *= inv;
    }
    __syncthreads();

    float4 acc[H_];
    #pragma unroll
    for (int h = 0; h < H_; h++) acc[h] = make_float4(0.f, 0.f, 0.f, 0.f);
    for (int p = 0; p < P_; p++) {
        float4 xv = ((const float4*)g_kv)[(size_t)(b * P_ + p) * 256 + tid];
        #pragma unroll
        for (int h = 0; h < H_; h++) {
            float a = sc[h * P_ + p];
            acc[h].x = fmaf(a, xv.x, acc[h].x); acc[h].y = fmaf(a, xv.y, acc[h].y);
            acc[h].z = fmaf(a, xv.z, acc[h].z); acc[h].w = fmaf(a, xv.w, acc[h].w);
        }
    }
    #pragma unroll
    for (int h = 0; h < H_; h++) {
        uint2 uh, ul;
        sp2(acc[h].x, acc[h].y, uh.x, ul.x);
        sp2(acc[h].z, acc[h].w, uh.y, ul.y);
        size_t o = (size_t)(h * B_ + b) * 256 + tid;
        ((uint2*)g_mx2_h)[o] = uh;
        ((uint2*)g_mx2_l)[o] = ul;
    }
}

__global__ __launch_bounds__(256) void k_logits(const float* __restrict__ w2,
                                                const float* __restrict__ b2,
                                                float* __restrict__ out) {
    int b = blockIdx.x, tid = threadIdx.x, w = tid >> 5, lane = tid & 31;
    const float* hrow = g_hid + (size_t)b * MH;
    for (int c = w; c < NC; c += 8) {
        float s = 0.f;
        for (int i = lane; i < MH; i += 32) s = fmaf(hrow[i], w2[(size_t)i * NC + c], s);
        #pragma unroll
        for (int o = 16; o; o >>= 1) s += __shfl_xor_sync(0xffffffffu, s, o);
        if (lane == 0) out[b * NC + c] = s + b2[c];
    }
}

// ---------------- launch ----------------
extern "C" void kernel_launch(void* const* d_in, const int* in_sizes, int n_in,
                              void* d_out, int out_size) {
    (void)in_sizes; (void)n_in; (void)out_size;
    const float* x    = (const float*)d_in[0];
    const float* chq  = (const float*)d_in[1];
    const float* clq  = (const float*)d_in[2];
    const float* chw  = (const float*)d_in[3];
    const float* chb  = (const float*)d_in[4];
    const float* chow = (const float*)d_in[5];
    const float* chob = (const float*)d_in[6];
    const float* tw   = (const float*)d_in[7];
    const float* tb   = (const float*)d_in[8];
    const float* tow  = (const float*)d_in[9];
    const float* tob  = (const float*)d_in[10];
    const float* qn_g = (const float*)d_in[11];
    const float* qn_b = (const float*)d_in[12];
    const float* cn_g = (const float*)d_in[13];
    const float* cn_b = (const float*)d_in[14];
    const float* pnc_g = (const float*)d_in[15];
    const float* pnc_b = (const float*)d_in[16];
    const float* pnp_g = (const float*)d_in[17];
    const float* pnp_b = (const float*)d_in[18];
    const float* pon_g = (const float*)d_in[19];
    const float* pon_b = (const float*)d_in[20];
    const float* w1 = (const float*)d_in[21];
    const float* b1 = (const float*)d_in[22];
    const float* w2 = (const float*)d_in[23];
    const float* b2 = (const float*)d_in[24];
    float* out = (float*)d_out;

    float *p_z, *p_p2, *p_hid;
    bf16 *mxh, *mxl, *plh, *pll, *m2h, *m2l, *p2h, *p2l, *lnh, *lnl;
    bf16 *wvh, *wvl, *cwh, *cwl, *w2h, *w2l, *toh, *tol, *w1h, *w1l;
    cudaGetSymbolAddress((void**)&p_z, g_z);
    cudaGetSymbolAddress((void**)&p_p2, g_p2);
    cudaGetSymbolAddress((void**)&p_hid, g_hid);
    cudaGetSymbolAddress((void**)&mxh, g_mx_h);     cudaGetSymbolAddress((void**)&mxl, g_mx_l);
    cudaGetSymbolAddress((void**)&plh, g_pooled_h); cudaGetSymbolAddress((void**)&pll, g_pooled_l);
    cudaGetSymbolAddress((void**)&m2h, g_mx2_h);    cudaGetSymbolAddress((void**)&m2l, g_mx2_l);
    cudaGetSymbolAddress((void**)&p2h, g_pooled2_h);cudaGetSymbolAddress((void**)&p2l, g_pooled2_l);
    cudaGetSymbolAddress((void**)&lnh, g_p2ln_h);   cudaGetSymbolAddress((void**)&lnl, g_p2ln_l);
    cudaGetSymbolAddress((void**)&wvh, g_wvT_h);    cudaGetSymbolAddress((void**)&wvl, g_wvT_l);
    cudaGetSymbolAddress((void**)&cwh, g_chowT_h);  cudaGetSymbolAddress((void**)&cwl, g_chowT_l);
    cudaGetSymbolAddress((void**)&w2h, g_wv2T_h);   cudaGetSymbolAddress((void**)&w2l, g_wv2T_l);
    cudaGetSymbolAddress((void**)&toh, g_towT_h);   cudaGetSymbolAddress((void**)&tol, g_towT_l);
    cudaGetSymbolAddress((void**)&w1h, g_w1T_h);    cudaGetSymbolAddress((void**)&w1l, g_w1T_l);

    cudaFuncSetAttribute(k_main, cudaFuncAttributeMaxDynamicSharedMemorySize, SMEM_MAIN);
    cudaFuncSetAttribute(k_mma, cudaFuncAttributeMaxDynamicSharedMemorySize, 3 * STG_B);
    const int MMS = 3 * STG_B;

    k_lnq<<<2, 256>>>(chq, clq, qn_g, qn_b, pnc_g, pnc_b);                  // 0
    k_qh<<<dim3(8, 2, 8), 128>>>(chw, tw);                                  // 1
    k_fold<<<dim3(512, 2), 128>>>(chw, chb, tw, tb);                        // 2
    k_main<<<dim3(P_, B_), 256, SMEM_MAIN>>>(x);                            // 3 <- captured
    k_trsplit<<<dim3(32, 32), 256>>>(chw, C3F, 2 * F_, wvh, wvl);           // 4
    k_mma<<<dim3(1, T_ / 128, H_), 256, MMS>>>(mxh, mxl, (long long)T_ * F_,
        wvh, wvl, (long long)64 * F_, chb + 2 * F_, 64,
        nullptr, plh, pll, F_, 64, 2);                                      // 5
    k_trsplit<<<dim3(32, 32), 256>>>(chow, F_, 0, cwh, cwl);                // 6
    k_mma<<<dim3(F_ / 64, T_ / 128, 1), 256, MMS>>>(plh, pll, 0,
        cwh, cwl, 0, chob, 0, p_z, nullptr, nullptr, F_, 0, 0);             // 7
    k_lnln<<<T_, 256>>>(cn_g, cn_b, pnp_g, pnp_b);                          // 8
    k_sc2mix<<<B_, 256>>>();                                                // 9
    k_trsplit<<<dim3(32, 32), 256>>>(tw, C3F, 2 * F_, w2h, w2l);            // 10
    k_mma<<<dim3(1, 1, H_), 256, MMS>>>(m2h, m2l, (long long)B_ * F_,
        w2h, w2l, (long long)64 * F_, tb + 2 * F_, 64,
        nullptr, p2h, p2l, F_, 64, 2);                                      // 11
    k_trsplit<<<dim3(32, 32), 256>>>(tow, F_, 0, toh, tol);                 // 12
    k_mma<<<dim3(F_ / 64, 1, 1), 256, MMS>>>(p2h, p2l, 0,
        toh, tol, 0, tob, 0, p_p2, nullptr, nullptr, F_, 0, 0);             // 13
    k_ln_split<<<B_, 256>>>(p_p2, pon_g, pon_b, lnh, lnl);                  // 14
    k_trsplit<<<dim3(32, 128), 256>>>(w1, MH, 0, w1h, w1l);                 // 15
    k_mma<<<dim3(MH / 64, 1, 1), 256, MMS>>>(lnh, lnl, 0,
        w1h, w1l, 0, b1, 0, p_hid, nullptr, nullptr, MH, 0, 1);             // 16
    k_logits<<<B_, 256>>>(w2, b2, out);                                     // 17
}